// round 11
// baseline (speedup 1.0000x reference)
#include <cuda_runtime.h>
#include <math.h>
#include <stdint.h>

#define Bn 8
#define Ln 8
#define Cn 64
#define Hn 56
#define Wn 56
#define HWn 3136
#define BCn (Bn*Cn)        // 512
#define BLn (Bn*Ln)        // 64
#define NTOT (BLn*Cn*HWn)  // 12,845,056
#define KWC 29             // compact kw count (Hermitian half)
#define NPOS (56*KWC)      // 1624 positions per slab
#define TILES 28           // k4t: 2 output rows per tile
#define NBLK (BLn*TILES)   // 1792 BN-partial slots

typedef unsigned long long u64;

__device__ __forceinline__ u64 ffma2(u64 a, u64 b, u64 c) {
    u64 d;
    asm("fma.rn.f32x2 %0, %1, %2, %3;" : "=l"(d) : "l"(a), "l"(b), "l"(c));
    return d;
}
__device__ __forceinline__ u64 pack2(float lo, float hi) {
    u64 d;
    asm("mov.b64 %0, {%1, %2};" : "=l"(d) : "f"(lo), "f"(hi));
    return d;
}
__device__ __forceinline__ float2 unpack2(u64 v) {
    float2 r;
    asm("mov.b64 {%0, %1}, %2;" : "=f"(r.x), "=f"(r.y) : "l"(v));
    return r;
}
__device__ __forceinline__ uint32_t f2tf32(float v) {
    uint32_t b;
    asm("cvt.rna.tf32.f32 %0, %1;" : "=r"(b) : "f"(v));
    return b;
}
__device__ __forceinline__ void mma_tf32(float* d, const uint32_t* a, const uint32_t* b) {
    asm volatile(
        "mma.sync.aligned.m16n8k8.row.col.f32.tf32.tf32.f32 "
        "{%0,%1,%2,%3}, {%4,%5,%6,%7}, {%8,%9}, {%0,%1,%2,%3};\n"
        : "+f"(d[0]), "+f"(d[1]), "+f"(d[2]), "+f"(d[3])
        : "r"(a[0]), "r"(a[1]), "r"(a[2]), "r"(a[3]), "r"(b[0]), "r"(b[1]));
}

// ---------------- scratch (device globals; no runtime allocation) ----------
__device__ float2 g_F2[BCn*Ln*NPOS];    // compact 2D-DFT (kw<=28) ~53MB
__device__ float  g_y[NTOT];            // pre-BN conv output (~51MB)
__device__ float  g_ppart[BCn*4*Ln];    // pooled partials
__device__ float  g_s[BLn*Cn];          // per (b,l,ci) input-channel scale
__device__ float  g_fb[BLn*Cn];         // per (b,l,co) dynamic bias
__device__ __align__(16) uint32_t g_Atf[72*512];  // tf32 weights, swizzled [kkg][co][8]
__device__ float  g_bnsum2[Cn*NBLK];
__device__ float  g_bnsq2[Cn*NBLK];
__device__ float  g_mean[Cn];
__device__ float  g_invstd[Cn];

// ============================================================================
// K0: one-shot A preparation: convw -> tf32, laid out [kkg][co][pair j] with
// the smem bank-swizzle (tg ^ (co&3)) baked in so block staging is raw copy.
// ============================================================================
__global__ __launch_bounds__(512) void k0_aprep(const float* __restrict__ convw) {
    int e = blockIdx.x*512 + threadIdx.x;   // 72*512 = 36864
    int j  = e & 1;  int t = e >> 1;
    int tg = t & 3;  t >>= 2;
    int co = t & 63; int kkg = t >> 6;      // 0..71
    int k  = kkg*8 + tg + 4*j;
    int ci = k / 9, tap = k - 9*ci;
    g_Atf[kkg*512 + co*8 + ((tg ^ (co & 3)) << 1) + j] =
        f2tf32(convw[(co*64 + ci)*9 + tap]);
}

// ============================================================================
// K1: 2D DFT per (b,c,l) slab; TWO slabs per block. Hermitian compact store.
// (unchanged from best)
// ============================================================================
__global__ __launch_bounds__(224) void k1_dft2d(const float* __restrict__ x) {
    extern __shared__ char k1sm[];
    u64*   t1a = (u64*)k1sm;
    u64*   t1s = t1a + 2*56*33;
    u64*   twp = t1s + 2*56*33;
    u64*   twA = twp + 56;
    u64*   twB = twA + 56;
    float* xs  = (float*)(twB + 56);

    int bid = blockIdx.x;
    int bc  = bid >> 2;
    int lp  = bid & 3;
    int b   = bc >> 6;
    int c   = bc & 63;
    int tid = threadIdx.x;
    int s   = (tid >= 112) ? 1 : 0;
    int loc = tid - s*112;
    int l   = lp*2 + s;

    float* xss = xs  + s*(56*57);
    u64*   t1A = t1a + s*(56*33);
    u64*   t1S = t1s + s*(56*33);

    const float* xp = x + (size_t)((b*Ln + l)*Cn + c) * HWn;
    #pragma unroll
    for (int k = 0; k < 28; ++k) {
        int e = loc + k*112;
        xss[(e/56)*57 + (e%56)] = xp[e];
    }
    if (tid < 56) {
        float sv, cv;
        sincosf(-6.28318530717958647692f * (float)tid / 56.0f, &sv, &cv);
        twp[tid] = pack2(cv, sv);
        twA[tid] = pack2(cv, cv);
        twB[tid] = pack2(-sv, sv);
    }
    __syncthreads();

    int th = loc >> 3;
    int tk = loc & 7;
    int h0  = th * 4;
    int kw0 = tk * 4;

    {
        u64 acc2[4][4];
        #pragma unroll
        for (int i = 0; i < 4; ++i)
            #pragma unroll
            for (int j = 0; j < 4; ++j) acc2[i][j] = 0ull;
        int idx[4] = {0, 0, 0, 0};
        for (int w = 0; w < 56; ++w) {
            u64 xa2[4];
            #pragma unroll
            for (int i = 0; i < 4; ++i) {
                float v = xss[(h0 + i)*57 + w];
                xa2[i] = pack2(v, v);
            }
            #pragma unroll
            for (int j = 0; j < 4; ++j) {
                u64 t = twp[idx[j]];
                #pragma unroll
                for (int i = 0; i < 4; ++i)
                    acc2[i][j] = ffma2(xa2[i], t, acc2[i][j]);
                idx[j] += kw0 + j;
                if (idx[j] >= 56) idx[j] -= 56;
            }
        }
        #pragma unroll
        for (int i = 0; i < 4; ++i)
            #pragma unroll
            for (int j = 0; j < 4; ++j) {
                int o = (h0 + i)*33 + kw0 + j;
                t1A[o] = acc2[i][j];
                float2 v = unpack2(acc2[i][j]);
                t1S[o] = pack2(v.y, v.x);
            }
    }
    __syncthreads();

    {
        u64 acc2[4][4];
        #pragma unroll
        for (int i = 0; i < 4; ++i)
            #pragma unroll
            for (int j = 0; j < 4; ++j) acc2[i][j] = 0ull;
        int idx[4] = {0, 0, 0, 0};
        for (int h = 0; h < 56; ++h) {
            u64 tA[4], tB[4];
            #pragma unroll
            for (int i = 0; i < 4; ++i) {
                tA[i] = twA[idx[i]];
                tB[i] = twB[idx[i]];
                idx[i] += h0 + i;
                if (idx[i] >= 56) idx[i] -= 56;
            }
            u64 ua[4], us[4];
            #pragma unroll
            for (int j = 0; j < 4; ++j) {
                ua[j] = t1A[h*33 + kw0 + j];
                us[j] = t1S[h*33 + kw0 + j];
            }
            #pragma unroll
            for (int i = 0; i < 4; ++i)
                #pragma unroll
                for (int j = 0; j < 4; ++j) {
                    acc2[i][j] = ffma2(tA[i], ua[j], acc2[i][j]);
                    acc2[i][j] = ffma2(tB[i], us[j], acc2[i][j]);
                }
        }
        float2* outp = g_F2 + (size_t)(bc*Ln + l) * NPOS;
        #pragma unroll
        for (int i = 0; i < 4; ++i) {
            int kh = h0 + i;
            #pragma unroll
            for (int j = 0; j < 4; ++j) {
                int kw = kw0 + j;
                if (kw <= 28) {
                    float2 v = unpack2(acc2[i][j]);
                    outp[kh*KWC + kw] = v;
                }
            }
        }
    }
}

// ============================================================================
// K2: 8-point DFT along L + magnitude; mirror reuse. (unchanged from best)
// ============================================================================
__global__ __launch_bounds__(448) void k2_ldft(const float* __restrict__ x) {
    int bx = blockIdx.x;
    int bc = bx >> 2, jb = bx & 3;
    int b  = bc >> 6, c = bc & 63;
    int tid = threadIdx.x;
    int idx = jb * 448 + tid;

    float contrib[8];
    #pragma unroll
    for (int k = 0; k < 8; ++k) contrib[k] = 0.f;

    if (idx < NPOS) {
        int kh = idx / KWC, kw = idx % KWC;
        int p  = kh*56 + kw;
        int pm = ((56 - kh) % 56)*56 + ((56 - kw) % 56);
        bool do_m = (kw >= 1 && kw <= 27);

        const float2* f2 = g_F2 + (size_t)(bc*Ln) * NPOS + idx;
        float fr[8], fi[8];
        #pragma unroll
        for (int l2 = 0; l2 < 8; ++l2) {
            float2 v = f2[(size_t)l2 * NPOS];
            fr[l2] = v.x; fi[l2] = v.y;
        }

        const float RT = 0.70710678118654752f;
        const float twc[8] = {1.f,  RT, 0.f, -RT, -1.f, -RT, 0.f,  RT};
        const float tws[8] = {0.f, -RT, -1.f, -RT, 0.f,  RT, 1.f,  RT};
        const float SCALE = 0.01f / 158.39507568359375f;

        float mag[8];
        #pragma unroll
        for (int k = 0; k < 8; ++k) {
            float re = 0.f, im = 0.f;
            #pragma unroll
            for (int l2 = 0; l2 < 8; ++l2) {
                int j = (l2 * k) & 7;
                re += twc[j]*fr[l2] - tws[j]*fi[l2];
                im += twc[j]*fi[l2] + tws[j]*fr[l2];
            }
            mag[k] = sqrtf(re*re + im*im);
        }

        #pragma unroll
        for (int k = 0; k < 8; ++k) {
            const float* xl = x + (size_t)((b*Ln + k)*Cn + c) * HWn;
            float v = xl[p] * (1.0f + SCALE * mag[k]);
            if (do_m)
                v += xl[pm] * (1.0f + SCALE * mag[(8 - k) & 7]);
            contrib[k] = v;
        }
    }

    #pragma unroll
    for (int k = 0; k < 8; ++k)
        #pragma unroll
        for (int off = 16; off > 0; off >>= 1)
            contrib[k] += __shfl_down_sync(0xffffffff, contrib[k], off);

    __shared__ float ws[14][8];
    int wid = tid >> 5, lane = tid & 31;
    if (lane == 0) {
        #pragma unroll
        for (int k = 0; k < 8; ++k) ws[wid][k] = contrib[k];
    }
    __syncthreads();
    if (tid < 8) {
        float s = 0.f;
        #pragma unroll
        for (int w2 = 0; w2 < 14; ++w2) s += ws[w2][tid];
        g_ppart[(bc*4 + jb)*8 + tid] = s;
    }
}

// ============================================================================
// K3: pooled -> calibration. (unchanged from best)
// ============================================================================
__global__ __launch_bounds__(64) void k3_calib(
    const float* __restrict__ tw_, const float* __restrict__ tb,
    const float* __restrict__ fcw, const float* __restrict__ fcb,
    const float* __restrict__ convb)
{
    int bl = blockIdx.x;
    int b  = bl >> 3, l = bl & 7;
    int tid = threadIdx.x;

    __shared__ float pooled[64];
    __shared__ float fcp[65];

    float s = 0.f;
    #pragma unroll
    for (int j = 0; j < 4; ++j)
        s += g_ppart[((b*Cn + tid)*4 + j)*8 + l];
    float pv = s * (1.0f / 3136.0f);
    pooled[tid] = pv;
    fcp[tid] = fcw[tid] * pv;
    __syncthreads();

    float calib = tb[tid];
    #pragma unroll 8
    for (int c = 0; c < 64; ++c) calib += tw_[tid*64 + c] * pooled[c];
    g_s[bl*Cn + tid] = calib + 1.0f;

    if (tid == 0) {
        float f = fcb[0];
        for (int c = 0; c < 64; ++c) f += fcp[c];
        fcp[64] = f + 1.0f;
    }
    __syncthreads();
    g_fb[bl*Cn + tid] = convb[tid] * fcp[64];
}

// ============================================================================
// K4T v3: tf32 implicit-GEMM conv. Same skeleton as v2; xs pitches padded to
// powers of two (row 64, ci-stride 256) so B-fragment banks collapse to
// (dc + px) mod 32 -> <=2-way conflicts (was 3-4 way with 240/60 pitches).
// smem 104,704 B -> still 2 blocks/SM (209 KB).
// ============================================================================
#define K4T_SMEM ((16384 + 9216 + 576) * 4)   // 104,704 B

__global__ __launch_bounds__(448, 2) void k4t_conv(const float* __restrict__ x,
                                                   const float* __restrict__ convw) {
    extern __shared__ uint32_t dsm[];
    uint32_t* xs   = dsm;                   // 16384 u32: [64ci][4r][64 pitch]
    uint32_t* As   = dsm + 16384;           // 9216 u32: quarter [18kk][64co][8]
    uint32_t* kOff = dsm + 16384 + 9216;    // 576 u32
    __shared__ float ssh[64];
    __shared__ float red_s[14][32];
    __shared__ float red_q[14][32];

    int tile = blockIdx.x;   // 0..27
    int bl   = blockIdx.y;   // 0..63
    int tid  = threadIdx.x;
    int w    = tid >> 5;
    int lane = tid & 31;
    int g    = lane >> 2;    // 0..7
    int tg   = lane & 3;     // 0..3
    int mw   = w & 1;
    int nw   = w >> 1;       // 0..6
    int mwbase = mw * 32;

    if (tid < 64) ssh[tid] = g_s[bl*64 + tid];
    for (int k = tid; k < 576; k += 448) {
        int ci = k / 9, tap = k - 9*ci, dr = tap / 3, dc = tap - 3*dr;
        kOff[k] = (uint32_t)(ci*256 + dr*64 + dc);
    }
    __syncthreads();        // ssh ready before xs staging uses it

    const float* xb = x + (size_t)bl * 64 * HWn;
    for (int e = tid; e < 64*4*58; e += 448) {
        int c = e % 58; int t = e / 58; int r = t & 3; int ci = t >> 2;
        int gr = 2*tile - 1 + r; int gc = c - 1;
        float v = 0.f;
        if (gr >= 0 && gr < 56 && gc >= 0 && gc < 56)
            v = xb[ci*HWn + gr*56 + gc] * ssh[ci];
        xs[ci*256 + r*64 + c] = f2tf32(v);
    }

    uint32_t pxoff[2];
    #pragma unroll
    for (int nf = 0; nf < 2; ++nf) {
        int px = nw*16 + nf*8 + g;
        int rs = (px >= 56) ? 1 : 0;
        pxoff[nf] = (uint32_t)(rs*64 + (px - rs*56));
    }
    int swz = ((tg ^ (g & 3)) << 1);

    float acc[2][2][4];
    #pragma unroll
    for (int mf = 0; mf < 2; ++mf)
        #pragma unroll
        for (int nf = 0; nf < 2; ++nf)
            #pragma unroll
            for (int j = 0; j < 4; ++j) acc[mf][nf][j] = 0.f;

    for (int q = 0; q < 4; ++q) {
        // stage A quarter: raw uint4 copy (swizzle baked in by k0)
        __syncthreads();    // prior quarter's As reads done; xs ready on q=0
        {
            const uint4* srcv = (const uint4*)(g_Atf + q*9216);
            uint4* dstv = (uint4*)As;
            for (int e = tid; e < 2304; e += 448) dstv[e] = srcv[e];
        }
        __syncthreads();

        int kbase = q*144;
        #pragma unroll 2
        for (int kk = 0; kk < 18; ++kk) {
            uint32_t ko0 = kOff[kbase + kk*8 + tg];
            uint32_t ko4 = kOff[kbase + kk*8 + tg + 4];

            uint32_t a[2][4];
            #pragma unroll
            for (int mf = 0; mf < 2; ++mf) {
                const uint32_t* base0 = As + kk*512 + (mwbase + mf*16 + g)*8 + swz;
                uint2 p0 = *(const uint2*)base0;          // rows g:   (a0, a2)
                uint2 p1 = *(const uint2*)(base0 + 64);   // rows g+8: (a1, a3)
                a[mf][0] = p0.x; a[mf][1] = p1.x; a[mf][2] = p0.y; a[mf][3] = p1.y;
            }
            uint32_t b[2][2];
            #pragma unroll
            for (int nf = 0; nf < 2; ++nf) {
                b[nf][0] = xs[ko0 + pxoff[nf]];
                b[nf][1] = xs[ko4 + pxoff[nf]];
            }
            #pragma unroll
            for (int mf = 0; mf < 2; ++mf)
                #pragma unroll
                for (int nf = 0; nf < 2; ++nf)
                    mma_tf32(acc[mf][nf], a[mf], b[nf]);
        }
    }
    __syncthreads();

    // ---- epilogue: + fb + residual, write y, BN partials -------------------
    float psum[2][2] = {{0.f,0.f},{0.f,0.f}};
    float psq [2][2] = {{0.f,0.f},{0.f,0.f}};
    #pragma unroll
    for (int mf = 0; mf < 2; ++mf) {
        #pragma unroll
        for (int nf = 0; nf < 2; ++nf) {
            #pragma unroll
            for (int j = 0; j < 4; ++j) {
                int hi = j >> 1;
                int co = mwbase + mf*16 + g + hi*8;
                int px = nw*16 + nf*8 + tg*2 + (j & 1);
                int rs = (px >= 56) ? 1 : 0;
                int row = 2*tile + rs;
                int col = px - rs*56;
                int loc = co*HWn + row*56 + col;
                float v = acc[mf][nf][j] + g_fb[bl*64 + co] + xb[loc];
                g_y[(size_t)bl*64*HWn + loc] = v;
                psum[mf][hi] += v;
                psq [mf][hi] += v*v;
            }
        }
    }
    #pragma unroll
    for (int mf = 0; mf < 2; ++mf)
        #pragma unroll
        for (int hi = 0; hi < 2; ++hi) {
            float s = psum[mf][hi], q = psq[mf][hi];
            s += __shfl_down_sync(0xffffffffu, s, 2, 4);
            s += __shfl_down_sync(0xffffffffu, s, 1, 4);
            q += __shfl_down_sync(0xffffffffu, q, 2, 4);
            q += __shfl_down_sync(0xffffffffu, q, 1, 4);
            if (tg == 0) {
                red_s[w][mf*16 + hi*8 + g] = s;
                red_q[w][mf*16 + hi*8 + g] = q;
            }
        }
    __syncthreads();
    if (tid < 64) {
        int co = tid;
        int mw2 = co >> 5; int rem = co & 31;
        int mf = rem >> 4; int g8 = rem & 15;
        int hi = g8 >> 3;  int g2 = g8 & 7;
        int idx = mf*16 + hi*8 + g2;
        float s = 0.f, q = 0.f;
        #pragma unroll
        for (int nw2 = 0; nw2 < 7; ++nw2) {
            s += red_s[nw2*2 + mw2][idx];
            q += red_q[nw2*2 + mw2][idx];
        }
        g_bnsum2[co*NBLK + bl*TILES + tile] = s;
        g_bnsq2 [co*NBLK + bl*TILES + tile] = q;
    }
}

// ============================================================================
// K4b: final BN statistics. 64 blocks, deterministic reduce over 1792.
// ============================================================================
__global__ __launch_bounds__(256) void k4b_stats() {
    int co  = blockIdx.x;
    int tid = threadIdx.x;
    float s = 0.f, q = 0.f;
    for (int i = tid; i < NBLK; i += 256) {
        s += g_bnsum2[co*NBLK + i];
        q += g_bnsq2 [co*NBLK + i];
    }
    #pragma unroll
    for (int off = 16; off > 0; off >>= 1) {
        s += __shfl_down_sync(0xffffffffu, s, off);
        q += __shfl_down_sync(0xffffffffu, q, off);
    }
    __shared__ float ws2[8], wq2[8];
    int wid = tid >> 5, lane = tid & 31;
    if (lane == 0) { ws2[wid] = s; wq2[wid] = q; }
    __syncthreads();
    if (tid == 0) {
        float S = 0.f, Q = 0.f;
        #pragma unroll
        for (int i = 0; i < 8; ++i) { S += ws2[i]; Q += wq2[i]; }
        const float invN = 1.0f / (float)(BLn * HWn);
        float mean = S * invN;
        float var  = Q * invN - mean*mean;
        g_mean[co]   = mean;
        g_invstd[co] = rsqrtf(var + 1e-5f);
    }
}

// ============================================================================
// K5: BN normalize + affine + SiLU -> d_out (unchanged)
// ============================================================================
__global__ __launch_bounds__(256) void k5_bnsilu(const float* __restrict__ gamma,
                                                 const float* __restrict__ beta,
                                                 float* __restrict__ out) {
    int i4 = blockIdx.x * 256 + threadIdx.x;
    int c = ((i4 * 4) / HWn) & 63;
    float4 y = ((const float4*)g_y)[i4];
    float m = g_mean[c], is = g_invstd[c] * gamma[c], bt = beta[c];
    float4 o;
    o.x = (y.x - m) * is + bt;
    o.y = (y.y - m) * is + bt;
    o.z = (y.z - m) * is + bt;
    o.w = (y.w - m) * is + bt;
    o.x = o.x / (1.0f + __expf(-o.x));
    o.y = o.y / (1.0f + __expf(-o.y));
    o.z = o.z / (1.0f + __expf(-o.z));
    o.w = o.w / (1.0f + __expf(-o.w));
    ((float4*)out)[i4] = o;
}

// ============================================================================
extern "C" void kernel_launch(void* const* d_in, const int* in_sizes, int n_in,
                              void* d_out, int out_size) {
    const float* x          = (const float*)d_in[0];
    const float* temporal_w = (const float*)d_in[1];
    const float* temporal_b = (const float*)d_in[2];
    const float* fc_w       = (const float*)d_in[3];
    const float* fc_b       = (const float*)d_in[4];
    const float* conv_w     = (const float*)d_in[5];
    const float* conv_b     = (const float*)d_in[6];
    const float* bn_gamma   = (const float*)d_in[7];
    const float* bn_beta    = (const float*)d_in[8];
    float* out = (float*)d_out;

    const int K1_SMEM = (2*56*33*2)*8 + 3*56*8 + (2*56*57)*4;   // 86016 B
    static int configured = 0;
    if (!configured) {
        cudaFuncSetAttribute(k1_dft2d, cudaFuncAttributeMaxDynamicSharedMemorySize, K1_SMEM);
        cudaFuncSetAttribute(k4t_conv, cudaFuncAttributeMaxDynamicSharedMemorySize, K4T_SMEM);
        configured = 1;
    }

    k0_aprep<<<72, 512>>>(conv_w);
    k1_dft2d<<<BCn*Ln/2, 224, K1_SMEM>>>(x);
    k2_ldft<<<BCn*4, 448>>>(x);
    k3_calib<<<BLn, 64>>>(temporal_w, temporal_b, fc_w, fc_b, conv_b);
    k4t_conv<<<dim3(TILES, BLn), 448, K4T_SMEM>>>(x, conv_w);
    k4b_stats<<<Cn, 256>>>();
    k5_bnsilu<<<NTOT/1024, 256>>>(bn_gamma, bn_beta, out);
}

// round 12
// speedup vs baseline: 1.0589x; 1.0589x over previous
#include <cuda_runtime.h>
#include <math.h>
#include <stdint.h>

#define Bn 8
#define Ln 8
#define Cn 64
#define Hn 56
#define Wn 56
#define HWn 3136
#define BCn (Bn*Cn)        // 512
#define BLn (Bn*Ln)        // 64
#define NTOT (BLn*Cn*HWn)  // 12,845,056
#define KWC 29             // compact kw count (Hermitian half)
#define NPOS (56*KWC)      // 1624 positions per slab
#define TILES 28           // k4t: 2 output rows per tile
#define NBLK (BLn*TILES)   // 1792 BN-partial slots

__device__ __forceinline__ uint32_t f2tf32(float v) {
    uint32_t b;
    asm("cvt.rna.tf32.f32 %0, %1;" : "=r"(b) : "f"(v));
    return b;
}
__device__ __forceinline__ void mma_tf32(float* d, const uint32_t* a, const uint32_t* b) {
    asm volatile(
        "mma.sync.aligned.m16n8k8.row.col.f32.tf32.tf32.f32 "
        "{%0,%1,%2,%3}, {%4,%5,%6,%7}, {%8,%9}, {%0,%1,%2,%3};\n"
        : "+f"(d[0]), "+f"(d[1]), "+f"(d[2]), "+f"(d[3])
        : "r"(a[0]), "r"(a[1]), "r"(a[2]), "r"(a[3]), "r"(b[0]), "r"(b[1]));
}

// ---------------- scratch (device globals; no runtime allocation) ----------
__device__ float  g_F2re[BCn*Ln*NPOS];  // compact 2D-DFT real plane (~26.6MB)
__device__ float  g_F2im[BCn*Ln*NPOS];  // compact 2D-DFT imag plane
__device__ float  g_y[NTOT];            // pre-BN conv output (~51MB)
__device__ float  g_ppart[BCn*4*Ln];    // pooled partials
__device__ float  g_s[BLn*Cn];          // per (b,l,ci) input-channel scale
__device__ float  g_fb[BLn*Cn];         // per (b,l,co) dynamic bias
__device__ __align__(16) uint32_t g_Atf[72*512];  // tf32 conv weights, swizzled
__device__ uint32_t g_WB[64*64];        // tf32 stage-B twiddles [w][kw_re|kw_im]
__device__ uint32_t g_WC[112*112];      // tf32 stage-C twiddles [[C,-S],[S,C]]
__device__ float  g_bnsum2[Cn*NBLK];
__device__ float  g_bnsq2[Cn*NBLK];
__device__ float  g_mean[Cn];
__device__ float  g_invstd[Cn];

// ============================================================================
// K0a: one-shot conv-A preparation (unchanged from best).
// ============================================================================
__global__ __launch_bounds__(512) void k0_aprep(const float* __restrict__ convw) {
    int e = blockIdx.x*512 + threadIdx.x;   // 72*512 = 36864
    int j  = e & 1;  int t = e >> 1;
    int tg = t & 3;  t >>= 2;
    int co = t & 63; int kkg = t >> 6;      // 0..71
    int k  = kkg*8 + tg + 4*j;
    int ci = k / 9, tap = k - 9*ci;
    g_Atf[kkg*512 + co*8 + ((tg ^ (co & 3)) << 1) + j] =
        f2tf32(convw[(co*64 + ci)*9 + tap]);
}

// ============================================================================
// K0b: one-shot DFT twiddle preparation in tf32.
// WB[w][c]: c<32 -> cos(-2pi (w*c)%56 /56); c>=32 -> sin(... (c-32)); w>=56 -> 0
// WC[r][k]: [[C, -S],[S, C]] stacking for T2 = WC * [T1re; T1im]
// ============================================================================
__global__ __launch_bounds__(512) void k0_dft() {
    int idx = blockIdx.x*512 + threadIdx.x;
    const float TWO_PI = 6.28318530717958647692f;
    if (idx < 4096) {
        int r = idx >> 6, cc = idx & 63;
        float v = 0.f;
        if (r < 56) {
            int kw = cc & 31;
            float ang = -TWO_PI * (float)((r*kw) % 56) / 56.f;
            float sv, cv; sincosf(ang, &sv, &cv);
            v = (cc < 32) ? cv : sv;
        }
        g_WB[idx] = f2tf32(v);
    } else if (idx < 4096 + 12544) {
        int e = idx - 4096;
        int r = e / 112, k = e % 112;
        int rr = (r < 56) ? r : r - 56;
        int kk = (k < 56) ? k : k - 56;
        float ang = -TWO_PI * (float)((rr*kk) % 56) / 56.f;
        float sv, cv; sincosf(ang, &sv, &cv);
        float v;
        if (r < 56) v = (k < 56) ? cv : -sv;
        else        v = (k < 56) ? sv : cv;
        g_WC[e] = f2tf32(v);
    }
}

// ============================================================================
// K1T: tensor-core 2D DFT per slab. One block per (b,c,l), 256 threads.
// Stage B: T1(64x64) = Xs(64x56) @ WB(56x64)      [224 MMAs]
// Stage C: T2(112x32) = WC(112x112) @ [T1re;T1im] [392 MMAs]
// Fragment layouts identical to the verified k4t skeleton. Bank-audited
// smem pitches: Xs 57, WB 72, WC 116, T1 68. Dynamic smem 100,096 B.
// ============================================================================
#define K1T_SMEM (25024*4)

__global__ __launch_bounds__(256, 2) void k1t_dft(const float* __restrict__ x) {
    extern __shared__ uint32_t sm1[];
    uint32_t* Xs  = sm1;            // 64*57  = 3648
    uint32_t* WBs = sm1 + 3648;     // 56*72  = 4032
    uint32_t* WCs = sm1 + 7680;     // 112*116= 12992
    uint32_t* T1s = sm1 + 20672;    // 64*68  = 4352

    int slab = blockIdx.x;          // bc*8 + l
    int bc = slab >> 3, l = slab & 7;
    int b = bc >> 6, c = bc & 63;
    int tid = threadIdx.x;
    int wrp = tid >> 5, lane = tid & 31;
    int g = lane >> 2, tg = lane & 3;

    const float* xp = x + (size_t)((b*Ln + l)*Cn + c) * HWn;

    for (int e = tid; e < 3648; e += 256) Xs[e] = 0u;
    __syncthreads();
    for (int e = tid; e < 3136; e += 256) {
        int h = e / 56, ww = e % 56;
        Xs[h*57 + ww] = f2tf32(xp[e]);
    }
    for (int e = tid; e < 3584; e += 256)           // 56*64
        WBs[(e >> 6)*72 + (e & 63)] = g_WB[e];
    for (int e = tid; e < 12544; e += 256)
        WCs[(e / 112)*116 + (e % 112)] = g_WC[e];
    __syncthreads();

    // ---- Stage B: warp wrp -> m-tile (wrp&3), n-tiles (wrp>>2)*4 .. +3
    {
        int mt = wrp & 3;
        int ng = (wrp >> 2) * 4;
        float accB[4][4];
        #pragma unroll
        for (int i = 0; i < 4; ++i)
            #pragma unroll
            for (int j = 0; j < 4; ++j) accB[i][j] = 0.f;

        for (int k = 0; k < 7; ++k) {
            int ab = (mt*16 + g)*57 + k*8 + tg;
            uint32_t a[4];
            a[0] = Xs[ab];            a[1] = Xs[ab + 8*57];
            a[2] = Xs[ab + 4];        a[3] = Xs[ab + 8*57 + 4];
            int kb0 = (k*8 + tg)*72;
            int kb1 = (k*8 + tg + 4)*72;
            #pragma unroll
            for (int i = 0; i < 4; ++i) {
                int ncol = (ng + i)*8 + g;
                uint32_t bfr[2] = { WBs[kb0 + ncol], WBs[kb1 + ncol] };
                mma_tf32(accB[i], a, bfr);
            }
        }
        #pragma unroll
        for (int i = 0; i < 4; ++i)
            #pragma unroll
            for (int j = 0; j < 4; ++j) {
                int row = mt*16 + g + (j >> 1)*8;
                int col = (ng + i)*8 + tg*2 + (j & 1);
                T1s[row*68 + col] = f2tf32(accB[i][j]);
            }
    }
    __syncthreads();

    // ---- Stage C: 14 units (7 m-tiles x 2 n-halves); warp strided
    float* re = g_F2re + (size_t)slab * NPOS;
    float* im = g_F2im + (size_t)slab * NPOS;
    for (int u = wrp; u < 14; u += 8) {
        int mt = u >> 1, nh = u & 1;
        float accC[2][4];
        #pragma unroll
        for (int i = 0; i < 2; ++i)
            #pragma unroll
            for (int j = 0; j < 4; ++j) accC[i][j] = 0.f;

        for (int k = 0; k < 14; ++k) {
            int ab = (mt*16 + g)*116 + k*8 + tg;
            uint32_t a[4];
            a[0] = WCs[ab];           a[1] = WCs[ab + 8*116];
            a[2] = WCs[ab + 4];       a[3] = WCs[ab + 8*116 + 4];
            int off  = (k >= 7) ? 56 : 0;
            int coff = (k >= 7) ? 32 : 0;
            int hr = k*8 + tg - off;
            #pragma unroll
            for (int i = 0; i < 2; ++i) {
                int ncol = (nh*2 + i)*8 + g + coff;
                uint32_t bfr[2] = { T1s[hr*68 + ncol], T1s[(hr + 4)*68 + ncol] };
                mma_tf32(accC[i], a, bfr);
            }
        }
        #pragma unroll
        for (int i = 0; i < 2; ++i) {
            int nt = nh*2 + i;
            #pragma unroll
            for (int j = 0; j < 4; ++j) {
                int r  = mt*16 + g + (j >> 1)*8;
                int kw = nt*8 + tg*2 + (j & 1);
                if (kw <= 28) {
                    if (r < 56) re[r*KWC + kw] = accC[i][j];
                    else        im[(r - 56)*KWC + kw] = accC[i][j];
                }
            }
        }
    }
}

// ============================================================================
// K2: 8-point DFT along L + magnitude at compact positions; mirror reuse.
// (planar F2 reads; otherwise unchanged from best)
// ============================================================================
__global__ __launch_bounds__(448) void k2_ldft(const float* __restrict__ x) {
    int bx = blockIdx.x;
    int bc = bx >> 2, jb = bx & 3;
    int b  = bc >> 6, c = bc & 63;
    int tid = threadIdx.x;
    int idx = jb * 448 + tid;

    float contrib[8];
    #pragma unroll
    for (int k = 0; k < 8; ++k) contrib[k] = 0.f;

    if (idx < NPOS) {
        int kh = idx / KWC, kw = idx % KWC;
        int p  = kh*56 + kw;
        int pm = ((56 - kh) % 56)*56 + ((56 - kw) % 56);
        bool do_m = (kw >= 1 && kw <= 27);

        const float* f2r = g_F2re + (size_t)(bc*Ln) * NPOS + idx;
        const float* f2i = g_F2im + (size_t)(bc*Ln) * NPOS + idx;
        float fr[8], fi[8];
        #pragma unroll
        for (int l2 = 0; l2 < 8; ++l2) {
            fr[l2] = f2r[(size_t)l2 * NPOS];
            fi[l2] = f2i[(size_t)l2 * NPOS];
        }

        const float RT = 0.70710678118654752f;
        const float twc[8] = {1.f,  RT, 0.f, -RT, -1.f, -RT, 0.f,  RT};
        const float tws[8] = {0.f, -RT, -1.f, -RT, 0.f,  RT, 1.f,  RT};
        const float SCALE = 0.01f / 158.39507568359375f;

        float mag[8];
        #pragma unroll
        for (int k = 0; k < 8; ++k) {
            float re = 0.f, im = 0.f;
            #pragma unroll
            for (int l2 = 0; l2 < 8; ++l2) {
                int j = (l2 * k) & 7;
                re += twc[j]*fr[l2] - tws[j]*fi[l2];
                im += twc[j]*fi[l2] + tws[j]*fr[l2];
            }
            mag[k] = sqrtf(re*re + im*im);
        }

        #pragma unroll
        for (int k = 0; k < 8; ++k) {
            const float* xl = x + (size_t)((b*Ln + k)*Cn + c) * HWn;
            float v = xl[p] * (1.0f + SCALE * mag[k]);
            if (do_m)
                v += xl[pm] * (1.0f + SCALE * mag[(8 - k) & 7]);
            contrib[k] = v;
        }
    }

    #pragma unroll
    for (int k = 0; k < 8; ++k)
        #pragma unroll
        for (int off = 16; off > 0; off >>= 1)
            contrib[k] += __shfl_down_sync(0xffffffff, contrib[k], off);

    __shared__ float ws[14][8];
    int wid = tid >> 5, lane = tid & 31;
    if (lane == 0) {
        #pragma unroll
        for (int k = 0; k < 8; ++k) ws[wid][k] = contrib[k];
    }
    __syncthreads();
    if (tid < 8) {
        float s = 0.f;
        #pragma unroll
        for (int w2 = 0; w2 < 14; ++w2) s += ws[w2][tid];
        g_ppart[(bc*4 + jb)*8 + tid] = s;
    }
}

// ============================================================================
// K3: pooled -> calibration. (unchanged from best)
// ============================================================================
__global__ __launch_bounds__(64) void k3_calib(
    const float* __restrict__ tw_, const float* __restrict__ tb,
    const float* __restrict__ fcw, const float* __restrict__ fcb,
    const float* __restrict__ convb)
{
    int bl = blockIdx.x;
    int b  = bl >> 3, l = bl & 7;
    int tid = threadIdx.x;

    __shared__ float pooled[64];
    __shared__ float fcp[65];

    float s = 0.f;
    #pragma unroll
    for (int j = 0; j < 4; ++j)
        s += g_ppart[((b*Cn + tid)*4 + j)*8 + l];
    float pv = s * (1.0f / 3136.0f);
    pooled[tid] = pv;
    fcp[tid] = fcw[tid] * pv;
    __syncthreads();

    float calib = tb[tid];
    #pragma unroll 8
    for (int c = 0; c < 64; ++c) calib += tw_[tid*64 + c] * pooled[c];
    g_s[bl*Cn + tid] = calib + 1.0f;

    if (tid == 0) {
        float f = fcb[0];
        for (int c = 0; c < 64; ++c) f += fcp[c];
        fcp[64] = f + 1.0f;
    }
    __syncthreads();
    g_fb[bl*Cn + tid] = convb[tid] * fcp[64];
}

// ============================================================================
// K4T: tf32 implicit-GEMM conv (exact R10 measured-best version: pitches
// 240/60, scale folded into B, raw-copy A staging, K in 4 quarters).
// ============================================================================
#define K4T_SMEM ((15360 + 9216 + 576) * 4)   // 100,608 B

__global__ __launch_bounds__(448, 2) void k4t_conv(const float* __restrict__ x,
                                                   const float* __restrict__ convw) {
    extern __shared__ uint32_t dsm[];
    uint32_t* xs   = dsm;                   // 15360 u32: [64ci][4r][60]
    uint32_t* As   = dsm + 15360;           // 9216 u32: quarter [18kk][64co][8]
    uint32_t* kOff = dsm + 15360 + 9216;    // 576 u32
    __shared__ float ssh[64];
    __shared__ float red_s[14][32];
    __shared__ float red_q[14][32];

    int tile = blockIdx.x;   // 0..27
    int bl   = blockIdx.y;   // 0..63
    int tid  = threadIdx.x;
    int w    = tid >> 5;
    int lane = tid & 31;
    int g    = lane >> 2;    // 0..7
    int tg   = lane & 3;     // 0..3
    int mw   = w & 1;
    int nw   = w >> 1;       // 0..6
    int mwbase = mw * 32;

    if (tid < 64) ssh[tid] = g_s[bl*64 + tid];
    for (int k = tid; k < 576; k += 448) {
        int ci = k / 9, tap = k - 9*ci, dr = tap / 3, dc = tap - 3*dr;
        kOff[k] = (uint32_t)(ci*240 + dr*60 + dc);
    }
    __syncthreads();

    const float* xb = x + (size_t)bl * 64 * HWn;
    for (int e = tid; e < 64*4*58; e += 448) {
        int c = e % 58; int t = e / 58; int r = t & 3; int ci = t >> 2;
        int gr = 2*tile - 1 + r; int gc = c - 1;
        float v = 0.f;
        if (gr >= 0 && gr < 56 && gc >= 0 && gc < 56)
            v = xb[ci*HWn + gr*56 + gc] * ssh[ci];
        xs[ci*240 + r*60 + c] = f2tf32(v);
    }

    uint32_t pxoff[2];
    #pragma unroll
    for (int nf = 0; nf < 2; ++nf) {
        int px = nw*16 + nf*8 + g;
        int rs = (px >= 56) ? 1 : 0;
        pxoff[nf] = (uint32_t)(rs*60 + (px - rs*56));
    }
    int swz = ((tg ^ (g & 3)) << 1);

    float acc[2][2][4];
    #pragma unroll
    for (int mf = 0; mf < 2; ++mf)
        #pragma unroll
        for (int nf = 0; nf < 2; ++nf)
            #pragma unroll
            for (int j = 0; j < 4; ++j) acc[mf][nf][j] = 0.f;

    for (int q = 0; q < 4; ++q) {
        __syncthreads();
        {
            const uint4* srcv = (const uint4*)(g_Atf + q*9216);
            uint4* dstv = (uint4*)As;
            for (int e = tid; e < 2304; e += 448) dstv[e] = srcv[e];
        }
        __syncthreads();

        int kbase = q*144;
        #pragma unroll 2
        for (int kk = 0; kk < 18; ++kk) {
            uint32_t ko0 = kOff[kbase + kk*8 + tg];
            uint32_t ko4 = kOff[kbase + kk*8 + tg + 4];

            uint32_t a[2][4];
            #pragma unroll
            for (int mf = 0; mf < 2; ++mf) {
                const uint32_t* base0 = As + kk*512 + (mwbase + mf*16 + g)*8 + swz;
                uint2 p0 = *(const uint2*)base0;
                uint2 p1 = *(const uint2*)(base0 + 64);
                a[mf][0] = p0.x; a[mf][1] = p1.x; a[mf][2] = p0.y; a[mf][3] = p1.y;
            }
            uint32_t b[2][2];
            #pragma unroll
            for (int nf = 0; nf < 2; ++nf) {
                b[nf][0] = xs[ko0 + pxoff[nf]];
                b[nf][1] = xs[ko4 + pxoff[nf]];
            }
            #pragma unroll
            for (int mf = 0; mf < 2; ++mf)
                #pragma unroll
                for (int nf = 0; nf < 2; ++nf)
                    mma_tf32(acc[mf][nf], a[mf], b[nf]);
        }
    }
    __syncthreads();

    // ---- epilogue ----
    float psum[2][2] = {{0.f,0.f},{0.f,0.f}};
    float psq [2][2] = {{0.f,0.f},{0.f,0.f}};
    #pragma unroll
    for (int mf = 0; mf < 2; ++mf) {
        #pragma unroll
        for (int nf = 0; nf < 2; ++nf) {
            #pragma unroll
            for (int j = 0; j < 4; ++j) {
                int hi = j >> 1;
                int co = mwbase + mf*16 + g + hi*8;
                int px = nw*16 + nf*8 + tg*2 + (j & 1);
                int rs = (px >= 56) ? 1 : 0;
                int row = 2*tile + rs;
                int col = px - rs*56;
                int loc = co*HWn + row*56 + col;
                float v = acc[mf][nf][j] + g_fb[bl*64 + co] + xb[loc];
                g_y[(size_t)bl*64*HWn + loc] = v;
                psum[mf][hi] += v;
                psq [mf][hi] += v*v;
            }
        }
    }
    #pragma unroll
    for (int mf = 0; mf < 2; ++mf)
        #pragma unroll
        for (int hi = 0; hi < 2; ++hi) {
            float s = psum[mf][hi], q = psq[mf][hi];
            s += __shfl_down_sync(0xffffffffu, s, 2, 4);
            s += __shfl_down_sync(0xffffffffu, s, 1, 4);
            q += __shfl_down_sync(0xffffffffu, q, 2, 4);
            q += __shfl_down_sync(0xffffffffu, q, 1, 4);
            if (tg == 0) {
                red_s[w][mf*16 + hi*8 + g] = s;
                red_q[w][mf*16 + hi*8 + g] = q;
            }
        }
    __syncthreads();
    if (tid < 64) {
        int co = tid;
        int mw2 = co >> 5; int rem = co & 31;
        int mf = rem >> 4; int g8 = rem & 15;
        int hi = g8 >> 3;  int g2 = g8 & 7;
        int idx = mf*16 + hi*8 + g2;
        float s = 0.f, q = 0.f;
        #pragma unroll
        for (int nw2 = 0; nw2 < 7; ++nw2) {
            s += red_s[nw2*2 + mw2][idx];
            q += red_q[nw2*2 + mw2][idx];
        }
        g_bnsum2[co*NBLK + bl*TILES + tile] = s;
        g_bnsq2 [co*NBLK + bl*TILES + tile] = q;
    }
}

// ============================================================================
// K4b: final BN statistics. (unchanged from best)
// ============================================================================
__global__ __launch_bounds__(256) void k4b_stats() {
    int co  = blockIdx.x;
    int tid = threadIdx.x;
    float s = 0.f, q = 0.f;
    for (int i = tid; i < NBLK; i += 256) {
        s += g_bnsum2[co*NBLK + i];
        q += g_bnsq2 [co*NBLK + i];
    }
    #pragma unroll
    for (int off = 16; off > 0; off >>= 1) {
        s += __shfl_down_sync(0xffffffffu, s, off);
        q += __shfl_down_sync(0xffffffffu, q, off);
    }
    __shared__ float ws2[8], wq2[8];
    int wid = tid >> 5, lane = tid & 31;
    if (lane == 0) { ws2[wid] = s; wq2[wid] = q; }
    __syncthreads();
    if (tid == 0) {
        float S = 0.f, Q = 0.f;
        #pragma unroll
        for (int i = 0; i < 8; ++i) { S += ws2[i]; Q += wq2[i]; }
        const float invN = 1.0f / (float)(BLn * HWn);
        float mean = S * invN;
        float var  = Q * invN - mean*mean;
        g_mean[co]   = mean;
        g_invstd[co] = rsqrtf(var + 1e-5f);
    }
}

// ============================================================================
// K5: BN normalize + affine + SiLU -> d_out (unchanged)
// ============================================================================
__global__ __launch_bounds__(256) void k5_bnsilu(const float* __restrict__ gamma,
                                                 const float* __restrict__ beta,
                                                 float* __restrict__ out) {
    int i4 = blockIdx.x * 256 + threadIdx.x;
    int c = ((i4 * 4) / HWn) & 63;
    float4 y = ((const float4*)g_y)[i4];
    float m = g_mean[c], is = g_invstd[c] * gamma[c], bt = beta[c];
    float4 o;
    o.x = (y.x - m) * is + bt;
    o.y = (y.y - m) * is + bt;
    o.z = (y.z - m) * is + bt;
    o.w = (y.w - m) * is + bt;
    o.x = o.x / (1.0f + __expf(-o.x));
    o.y = o.y / (1.0f + __expf(-o.y));
    o.z = o.z / (1.0f + __expf(-o.z));
    o.w = o.w / (1.0f + __expf(-o.w));
    ((float4*)out)[i4] = o;
}

// ============================================================================
extern "C" void kernel_launch(void* const* d_in, const int* in_sizes, int n_in,
                              void* d_out, int out_size) {
    const float* x          = (const float*)d_in[0];
    const float* temporal_w = (const float*)d_in[1];
    const float* temporal_b = (const float*)d_in[2];
    const float* fc_w       = (const float*)d_in[3];
    const float* fc_b       = (const float*)d_in[4];
    const float* conv_w     = (const float*)d_in[5];
    const float* conv_b     = (const float*)d_in[6];
    const float* bn_gamma   = (const float*)d_in[7];
    const float* bn_beta    = (const float*)d_in[8];
    float* out = (float*)d_out;

    static int configured = 0;
    if (!configured) {
        cudaFuncSetAttribute(k1t_dft,  cudaFuncAttributeMaxDynamicSharedMemorySize, K1T_SMEM);
        cudaFuncSetAttribute(k4t_conv, cudaFuncAttributeMaxDynamicSharedMemorySize, K4T_SMEM);
        configured = 1;
    }

    k0_aprep<<<72, 512>>>(conv_w);
    k0_dft<<<33, 512>>>();
    k1t_dft<<<BCn*Ln, 256, K1T_SMEM>>>(x);        // 4096 blocks, tensor DFT
    k2_ldft<<<BCn*4, 448>>>(x);
    k3_calib<<<BLn, 64>>>(temporal_w, temporal_b, fc_w, fc_b, conv_b);
    k4t_conv<<<dim3(TILES, BLn), 448, K4T_SMEM>>>(x, conv_w);
    k4b_stats<<<Cn, 256>>>();
    k5_bnsilu<<<NTOT/1024, 256>>>(bn_gamma, bn_beta, out);
}

// round 13
// speedup vs baseline: 1.0684x; 1.0089x over previous
#include <cuda_runtime.h>
#include <cuda_fp16.h>
#include <math.h>
#include <stdint.h>

#define Bn 8
#define Ln 8
#define Cn 64
#define Hn 56
#define Wn 56
#define HWn 3136
#define BCn (Bn*Cn)        // 512
#define BLn (Bn*Ln)        // 64
#define NTOT (BLn*Cn*HWn)  // 12,845,056
#define KWC 29             // compact kw count (Hermitian half)
#define NPOS (56*KWC)      // 1624 positions per slab
#define TILES 28           // k4t: 2 output rows per tile
#define NBLK (BLn*TILES)   // 1792 BN-partial slots

__device__ __forceinline__ uint32_t f2tf32(float v) {
    uint32_t b;
    asm("cvt.rna.tf32.f32 %0, %1;" : "=r"(b) : "f"(v));
    return b;
}
__device__ __forceinline__ void mma_tf32(float* d, const uint32_t* a, const uint32_t* b) {
    asm volatile(
        "mma.sync.aligned.m16n8k8.row.col.f32.tf32.tf32.f32 "
        "{%0,%1,%2,%3}, {%4,%5,%6,%7}, {%8,%9}, {%0,%1,%2,%3};\n"
        : "+f"(d[0]), "+f"(d[1]), "+f"(d[2]), "+f"(d[3])
        : "r"(a[0]), "r"(a[1]), "r"(a[2]), "r"(a[3]), "r"(b[0]), "r"(b[1]));
}

// ---------------- scratch (device globals; no runtime allocation) ----------
__device__ float  g_F2re[BCn*Ln*NPOS];  // compact 2D-DFT real plane (~26.6MB)
__device__ float  g_F2im[BCn*Ln*NPOS];  // compact 2D-DFT imag plane
__device__ __half g_yh[NTOT];           // pre-BN conv output, fp16 (~25.7MB)
__device__ float  g_ppart[BCn*4*Ln];    // pooled partials
__device__ float  g_s[BLn*Cn];          // per (b,l,ci) input-channel scale
__device__ float  g_fb[BLn*Cn];         // per (b,l,co) dynamic bias
__device__ __align__(16) uint32_t g_Atf[72*512];  // tf32 conv weights, swizzled
__device__ uint32_t g_WB[64*64];        // tf32 stage-B twiddles
__device__ uint32_t g_WC[112*112];      // tf32 stage-C twiddles [[C,-S],[S,C]]
__device__ float  g_bnsum2[Cn*NBLK];
__device__ float  g_bnsq2[Cn*NBLK];
__device__ float  g_mean[Cn];
__device__ float  g_invstd[Cn];

// ============================================================================
// K0: merged one-shot prep: conv-A tf32 (swizzled) + DFT twiddles tf32.
// ============================================================================
__global__ __launch_bounds__(512) void k0_prep(const float* __restrict__ convw) {
    int e = blockIdx.x*512 + threadIdx.x;
    const float TWO_PI = 6.28318530717958647692f;
    if (e < 36864) {
        int j  = e & 1;  int t = e >> 1;
        int tg = t & 3;  t >>= 2;
        int co = t & 63; int kkg = t >> 6;      // 0..71
        int k  = kkg*8 + tg + 4*j;
        int ci = k / 9, tap = k - 9*ci;
        g_Atf[kkg*512 + co*8 + ((tg ^ (co & 3)) << 1) + j] =
            f2tf32(convw[(co*64 + ci)*9 + tap]);
    } else if (e < 36864 + 4096) {
        int idx = e - 36864;
        int r = idx >> 6, cc = idx & 63;
        float v = 0.f;
        if (r < 56) {
            int kw = cc & 31;
            float ang = -TWO_PI * (float)((r*kw) % 56) / 56.f;
            float sv, cv; sincosf(ang, &sv, &cv);
            v = (cc < 32) ? cv : sv;
        }
        g_WB[idx] = f2tf32(v);
    } else if (e < 36864 + 4096 + 12544) {
        int e2 = e - 36864 - 4096;
        int r = e2 / 112, k = e2 % 112;
        int rr = (r < 56) ? r : r - 56;
        int kk = (k < 56) ? k : k - 56;
        float ang = -TWO_PI * (float)((rr*kk) % 56) / 56.f;
        float sv, cv; sincosf(ang, &sv, &cv);
        float v;
        if (r < 56) v = (k < 56) ? cv : -sv;
        else        v = (k < 56) ? sv : cv;
        g_WC[e2] = f2tf32(v);
    }
}

// ============================================================================
// K1T: tensor-core 2D DFT per slab (unchanged from R12 winner).
// ============================================================================
#define K1T_SMEM (25024*4)

__global__ __launch_bounds__(256, 2) void k1t_dft(const float* __restrict__ x) {
    extern __shared__ uint32_t sm1[];
    uint32_t* Xs  = sm1;            // 64*57  = 3648
    uint32_t* WBs = sm1 + 3648;     // 56*72  = 4032
    uint32_t* WCs = sm1 + 7680;     // 112*116= 12992
    uint32_t* T1s = sm1 + 20672;    // 64*68  = 4352

    int slab = blockIdx.x;          // bc*8 + l
    int bc = slab >> 3, l = slab & 7;
    int b = bc >> 6, c = bc & 63;
    int tid = threadIdx.x;
    int wrp = tid >> 5, lane = tid & 31;
    int g = lane >> 2, tg = lane & 3;

    const float* xp = x + (size_t)((b*Ln + l)*Cn + c) * HWn;

    for (int e = tid; e < 3648; e += 256) Xs[e] = 0u;
    __syncthreads();
    for (int e = tid; e < 3136; e += 256) {
        int h = e / 56, ww = e % 56;
        Xs[h*57 + ww] = f2tf32(xp[e]);
    }
    for (int e = tid; e < 3584; e += 256)
        WBs[(e >> 6)*72 + (e & 63)] = g_WB[e];
    for (int e = tid; e < 12544; e += 256)
        WCs[(e / 112)*116 + (e % 112)] = g_WC[e];
    __syncthreads();

    // ---- Stage B
    {
        int mt = wrp & 3;
        int ng = (wrp >> 2) * 4;
        float accB[4][4];
        #pragma unroll
        for (int i = 0; i < 4; ++i)
            #pragma unroll
            for (int j = 0; j < 4; ++j) accB[i][j] = 0.f;

        for (int k = 0; k < 7; ++k) {
            int ab = (mt*16 + g)*57 + k*8 + tg;
            uint32_t a[4];
            a[0] = Xs[ab];            a[1] = Xs[ab + 8*57];
            a[2] = Xs[ab + 4];        a[3] = Xs[ab + 8*57 + 4];
            int kb0 = (k*8 + tg)*72;
            int kb1 = (k*8 + tg + 4)*72;
            #pragma unroll
            for (int i = 0; i < 4; ++i) {
                int ncol = (ng + i)*8 + g;
                uint32_t bfr[2] = { WBs[kb0 + ncol], WBs[kb1 + ncol] };
                mma_tf32(accB[i], a, bfr);
            }
        }
        #pragma unroll
        for (int i = 0; i < 4; ++i)
            #pragma unroll
            for (int j = 0; j < 4; ++j) {
                int row = mt*16 + g + (j >> 1)*8;
                int col = (ng + i)*8 + tg*2 + (j & 1);
                T1s[row*68 + col] = f2tf32(accB[i][j]);
            }
    }
    __syncthreads();

    // ---- Stage C
    float* re = g_F2re + (size_t)slab * NPOS;
    float* im = g_F2im + (size_t)slab * NPOS;
    for (int u = wrp; u < 14; u += 8) {
        int mt = u >> 1, nh = u & 1;
        float accC[2][4];
        #pragma unroll
        for (int i = 0; i < 2; ++i)
            #pragma unroll
            for (int j = 0; j < 4; ++j) accC[i][j] = 0.f;

        for (int k = 0; k < 14; ++k) {
            int ab = (mt*16 + g)*116 + k*8 + tg;
            uint32_t a[4];
            a[0] = WCs[ab];           a[1] = WCs[ab + 8*116];
            a[2] = WCs[ab + 4];       a[3] = WCs[ab + 8*116 + 4];
            int off  = (k >= 7) ? 56 : 0;
            int coff = (k >= 7) ? 32 : 0;
            int hr = k*8 + tg - off;
            #pragma unroll
            for (int i = 0; i < 2; ++i) {
                int ncol = (nh*2 + i)*8 + g + coff;
                uint32_t bfr[2] = { T1s[hr*68 + ncol], T1s[(hr + 4)*68 + ncol] };
                mma_tf32(accC[i], a, bfr);
            }
        }
        #pragma unroll
        for (int i = 0; i < 2; ++i) {
            int nt = nh*2 + i;
            #pragma unroll
            for (int j = 0; j < 4; ++j) {
                int r  = mt*16 + g + (j >> 1)*8;
                int kw = nt*8 + tg*2 + (j & 1);
                if (kw <= 28) {
                    if (r < 56) re[r*KWC + kw] = accC[i][j];
                    else        im[(r - 56)*KWC + kw] = accC[i][j];
                }
            }
        }
    }
}

// ============================================================================
// K2: 8-point DFT along L + magnitude; mirror reuse. (unchanged)
// ============================================================================
__global__ __launch_bounds__(448) void k2_ldft(const float* __restrict__ x) {
    int bx = blockIdx.x;
    int bc = bx >> 2, jb = bx & 3;
    int b  = bc >> 6, c = bc & 63;
    int tid = threadIdx.x;
    int idx = jb * 448 + tid;

    float contrib[8];
    #pragma unroll
    for (int k = 0; k < 8; ++k) contrib[k] = 0.f;

    if (idx < NPOS) {
        int kh = idx / KWC, kw = idx % KWC;
        int p  = kh*56 + kw;
        int pm = ((56 - kh) % 56)*56 + ((56 - kw) % 56);
        bool do_m = (kw >= 1 && kw <= 27);

        const float* f2r = g_F2re + (size_t)(bc*Ln) * NPOS + idx;
        const float* f2i = g_F2im + (size_t)(bc*Ln) * NPOS + idx;
        float fr[8], fi[8];
        #pragma unroll
        for (int l2 = 0; l2 < 8; ++l2) {
            fr[l2] = f2r[(size_t)l2 * NPOS];
            fi[l2] = f2i[(size_t)l2 * NPOS];
        }

        const float RT = 0.70710678118654752f;
        const float twc[8] = {1.f,  RT, 0.f, -RT, -1.f, -RT, 0.f,  RT};
        const float tws[8] = {0.f, -RT, -1.f, -RT, 0.f,  RT, 1.f,  RT};
        const float SCALE = 0.01f / 158.39507568359375f;

        float mag[8];
        #pragma unroll
        for (int k = 0; k < 8; ++k) {
            float re = 0.f, im = 0.f;
            #pragma unroll
            for (int l2 = 0; l2 < 8; ++l2) {
                int j = (l2 * k) & 7;
                re += twc[j]*fr[l2] - tws[j]*fi[l2];
                im += twc[j]*fi[l2] + tws[j]*fr[l2];
            }
            mag[k] = sqrtf(re*re + im*im);
        }

        #pragma unroll
        for (int k = 0; k < 8; ++k) {
            const float* xl = x + (size_t)((b*Ln + k)*Cn + c) * HWn;
            float v = xl[p] * (1.0f + SCALE * mag[k]);
            if (do_m)
                v += xl[pm] * (1.0f + SCALE * mag[(8 - k) & 7]);
            contrib[k] = v;
        }
    }

    #pragma unroll
    for (int k = 0; k < 8; ++k)
        #pragma unroll
        for (int off = 16; off > 0; off >>= 1)
            contrib[k] += __shfl_down_sync(0xffffffff, contrib[k], off);

    __shared__ float ws[14][8];
    int wid = tid >> 5, lane = tid & 31;
    if (lane == 0) {
        #pragma unroll
        for (int k = 0; k < 8; ++k) ws[wid][k] = contrib[k];
    }
    __syncthreads();
    if (tid < 8) {
        float s = 0.f;
        #pragma unroll
        for (int w2 = 0; w2 < 14; ++w2) s += ws[w2][tid];
        g_ppart[(bc*4 + jb)*8 + tid] = s;
    }
}

// ============================================================================
// K3: pooled -> calibration. (unchanged)
// ============================================================================
__global__ __launch_bounds__(64) void k3_calib(
    const float* __restrict__ tw_, const float* __restrict__ tb,
    const float* __restrict__ fcw, const float* __restrict__ fcb,
    const float* __restrict__ convb)
{
    int bl = blockIdx.x;
    int b  = bl >> 3, l = bl & 7;
    int tid = threadIdx.x;

    __shared__ float pooled[64];
    __shared__ float fcp[65];

    float s = 0.f;
    #pragma unroll
    for (int j = 0; j < 4; ++j)
        s += g_ppart[((b*Cn + tid)*4 + j)*8 + l];
    float pv = s * (1.0f / 3136.0f);
    pooled[tid] = pv;
    fcp[tid] = fcw[tid] * pv;
    __syncthreads();

    float calib = tb[tid];
    #pragma unroll 8
    for (int c = 0; c < 64; ++c) calib += tw_[tid*64 + c] * pooled[c];
    g_s[bl*Cn + tid] = calib + 1.0f;

    if (tid == 0) {
        float f = fcb[0];
        for (int c = 0; c < 64; ++c) f += fcp[c];
        fcp[64] = f + 1.0f;
    }
    __syncthreads();
    g_fb[bl*Cn + tid] = convb[tid] * fcp[64];
}

// ============================================================================
// K4T: tf32 implicit-GEMM conv (R10 measured-best mainloop); epilogue now
// stores y as packed half2 and computes BN partials from the ROUNDED values
// so k5's normalization matches the stored data exactly.
// ============================================================================
#define K4T_SMEM ((15360 + 9216 + 576) * 4)   // 100,608 B

__global__ __launch_bounds__(448, 2) void k4t_conv(const float* __restrict__ x,
                                                   const float* __restrict__ convw) {
    extern __shared__ uint32_t dsm[];
    uint32_t* xs   = dsm;                   // 15360 u32: [64ci][4r][60]
    uint32_t* As   = dsm + 15360;           // 9216 u32
    uint32_t* kOff = dsm + 15360 + 9216;    // 576 u32
    __shared__ float ssh[64];
    __shared__ float red_s[14][32];
    __shared__ float red_q[14][32];

    int tile = blockIdx.x;   // 0..27
    int bl   = blockIdx.y;   // 0..63
    int tid  = threadIdx.x;
    int w    = tid >> 5;
    int lane = tid & 31;
    int g    = lane >> 2;    // 0..7
    int tg   = lane & 3;     // 0..3
    int mw   = w & 1;
    int nw   = w >> 1;       // 0..6
    int mwbase = mw * 32;

    if (tid < 64) ssh[tid] = g_s[bl*64 + tid];
    for (int k = tid; k < 576; k += 448) {
        int ci = k / 9, tap = k - 9*ci, dr = tap / 3, dc = tap - 3*dr;
        kOff[k] = (uint32_t)(ci*240 + dr*60 + dc);
    }
    __syncthreads();

    const float* xb = x + (size_t)bl * 64 * HWn;
    for (int e = tid; e < 64*4*58; e += 448) {
        int c = e % 58; int t = e / 58; int r = t & 3; int ci = t >> 2;
        int gr = 2*tile - 1 + r; int gc = c - 1;
        float v = 0.f;
        if (gr >= 0 && gr < 56 && gc >= 0 && gc < 56)
            v = xb[ci*HWn + gr*56 + gc] * ssh[ci];
        xs[ci*240 + r*60 + c] = f2tf32(v);
    }

    uint32_t pxoff[2];
    #pragma unroll
    for (int nf = 0; nf < 2; ++nf) {
        int px = nw*16 + nf*8 + g;
        int rs = (px >= 56) ? 1 : 0;
        pxoff[nf] = (uint32_t)(rs*60 + (px - rs*56));
    }
    int swz = ((tg ^ (g & 3)) << 1);

    float acc[2][2][4];
    #pragma unroll
    for (int mf = 0; mf < 2; ++mf)
        #pragma unroll
        for (int nf = 0; nf < 2; ++nf)
            #pragma unroll
            for (int j = 0; j < 4; ++j) acc[mf][nf][j] = 0.f;

    for (int q = 0; q < 4; ++q) {
        __syncthreads();
        {
            const uint4* srcv = (const uint4*)(g_Atf + q*9216);
            uint4* dstv = (uint4*)As;
            for (int e = tid; e < 2304; e += 448) dstv[e] = srcv[e];
        }
        __syncthreads();

        int kbase = q*144;
        #pragma unroll 2
        for (int kk = 0; kk < 18; ++kk) {
            uint32_t ko0 = kOff[kbase + kk*8 + tg];
            uint32_t ko4 = kOff[kbase + kk*8 + tg + 4];

            uint32_t a[2][4];
            #pragma unroll
            for (int mf = 0; mf < 2; ++mf) {
                const uint32_t* base0 = As + kk*512 + (mwbase + mf*16 + g)*8 + swz;
                uint2 p0 = *(const uint2*)base0;
                uint2 p1 = *(const uint2*)(base0 + 64);
                a[mf][0] = p0.x; a[mf][1] = p1.x; a[mf][2] = p0.y; a[mf][3] = p1.y;
            }
            uint32_t b[2][2];
            #pragma unroll
            for (int nf = 0; nf < 2; ++nf) {
                b[nf][0] = xs[ko0 + pxoff[nf]];
                b[nf][1] = xs[ko4 + pxoff[nf]];
            }
            #pragma unroll
            for (int mf = 0; mf < 2; ++mf)
                #pragma unroll
                for (int nf = 0; nf < 2; ++nf)
                    mma_tf32(acc[mf][nf], a[mf], b[nf]);
        }
    }
    __syncthreads();

    // ---- epilogue: + fb + residual, half2-packed y stores, BN partials ----
    float psum[2][2] = {{0.f,0.f},{0.f,0.f}};
    float psq [2][2] = {{0.f,0.f},{0.f,0.f}};
    #pragma unroll
    for (int mf = 0; mf < 2; ++mf) {
        #pragma unroll
        for (int nf = 0; nf < 2; ++nf) {
            #pragma unroll
            for (int hi = 0; hi < 2; ++hi) {
                int co = mwbase + mf*16 + g + hi*8;
                float fbv = g_fb[bl*64 + co];
                int px0 = nw*16 + nf*8 + tg*2;       // even; pair (px0, px0+1)
                int rs = (px0 >= 56) ? 1 : 0;        // same rs for both (px0 even)
                int row = 2*tile + rs;
                int col = px0 - rs*56;
                int loc = co*HWn + row*56 + col;     // even -> half2 aligned
                float v0 = acc[mf][nf][hi*2 + 0] + fbv + xb[loc];
                float v1 = acc[mf][nf][hi*2 + 1] + fbv + xb[loc + 1];
                __half2 h2 = __floats2half2_rn(v0, v1);
                *(__half2*)(g_yh + (size_t)bl*64*HWn + loc) = h2;
                float r0 = __half2float(__low2half(h2));
                float r1 = __half2float(__high2half(h2));
                psum[mf][hi] += r0 + r1;
                psq [mf][hi] += r0*r0 + r1*r1;
            }
        }
    }
    #pragma unroll
    for (int mf = 0; mf < 2; ++mf)
        #pragma unroll
        for (int hi = 0; hi < 2; ++hi) {
            float s = psum[mf][hi], q = psq[mf][hi];
            s += __shfl_down_sync(0xffffffffu, s, 2, 4);
            s += __shfl_down_sync(0xffffffffu, s, 1, 4);
            q += __shfl_down_sync(0xffffffffu, q, 2, 4);
            q += __shfl_down_sync(0xffffffffu, q, 1, 4);
            if (tg == 0) {
                red_s[w][mf*16 + hi*8 + g] = s;
                red_q[w][mf*16 + hi*8 + g] = q;
            }
        }
    __syncthreads();
    if (tid < 64) {
        int co = tid;
        int mw2 = co >> 5; int rem = co & 31;
        int mf = rem >> 4; int g8 = rem & 15;
        int hi = g8 >> 3;  int g2 = g8 & 7;
        int idx = mf*16 + hi*8 + g2;
        float s = 0.f, q = 0.f;
        #pragma unroll
        for (int nw2 = 0; nw2 < 7; ++nw2) {
            s += red_s[nw2*2 + mw2][idx];
            q += red_q[nw2*2 + mw2][idx];
        }
        g_bnsum2[co*NBLK + bl*TILES + tile] = s;
        g_bnsq2 [co*NBLK + bl*TILES + tile] = q;
    }
}

// ============================================================================
// K4b: final BN statistics. (unchanged)
// ============================================================================
__global__ __launch_bounds__(256) void k4b_stats() {
    int co  = blockIdx.x;
    int tid = threadIdx.x;
    float s = 0.f, q = 0.f;
    for (int i = tid; i < NBLK; i += 256) {
        s += g_bnsum2[co*NBLK + i];
        q += g_bnsq2 [co*NBLK + i];
    }
    #pragma unroll
    for (int off = 16; off > 0; off >>= 1) {
        s += __shfl_down_sync(0xffffffffu, s, off);
        q += __shfl_down_sync(0xffffffffu, q, off);
    }
    __shared__ float ws2[8], wq2[8];
    int wid = tid >> 5, lane = tid & 31;
    if (lane == 0) { ws2[wid] = s; wq2[wid] = q; }
    __syncthreads();
    if (tid == 0) {
        float S = 0.f, Q = 0.f;
        #pragma unroll
        for (int i = 0; i < 8; ++i) { S += ws2[i]; Q += wq2[i]; }
        const float invN = 1.0f / (float)(BLn * HWn);
        float mean = S * invN;
        float var  = Q * invN - mean*mean;
        g_mean[co]   = mean;
        g_invstd[co] = rsqrtf(var + 1e-5f);
    }
}

// ============================================================================
// K5: BN normalize + affine + SiLU -> d_out; reads fp16 y (uint2 = 4 halves).
// ============================================================================
__global__ __launch_bounds__(256) void k5_bnsilu(const float* __restrict__ gamma,
                                                 const float* __restrict__ beta,
                                                 float* __restrict__ out) {
    int i4 = blockIdx.x * 256 + threadIdx.x;
    int c = ((i4 * 4) / HWn) & 63;
    uint2 yv = ((const uint2*)g_yh)[i4];
    __half2 h01 = *(__half2*)&yv.x;
    __half2 h23 = *(__half2*)&yv.y;
    float2 f01 = __half22float2(h01);
    float2 f23 = __half22float2(h23);
    float m = g_mean[c], is = g_invstd[c] * gamma[c], bt = beta[c];
    float4 o;
    o.x = (f01.x - m) * is + bt;
    o.y = (f01.y - m) * is + bt;
    o.z = (f23.x - m) * is + bt;
    o.w = (f23.y - m) * is + bt;
    o.x = o.x / (1.0f + __expf(-o.x));
    o.y = o.y / (1.0f + __expf(-o.y));
    o.z = o.z / (1.0f + __expf(-o.z));
    o.w = o.w / (1.0f + __expf(-o.w));
    ((float4*)out)[i4] = o;
}

// ============================================================================
extern "C" void kernel_launch(void* const* d_in, const int* in_sizes, int n_in,
                              void* d_out, int out_size) {
    const float* x          = (const float*)d_in[0];
    const float* temporal_w = (const float*)d_in[1];
    const float* temporal_b = (const float*)d_in[2];
    const float* fc_w       = (const float*)d_in[3];
    const float* fc_b       = (const float*)d_in[4];
    const float* conv_w     = (const float*)d_in[5];
    const float* conv_b     = (const float*)d_in[6];
    const float* bn_gamma   = (const float*)d_in[7];
    const float* bn_beta    = (const float*)d_in[8];
    float* out = (float*)d_out;

    static int configured = 0;
    if (!configured) {
        cudaFuncSetAttribute(k1t_dft,  cudaFuncAttributeMaxDynamicSharedMemorySize, K1T_SMEM);
        cudaFuncSetAttribute(k4t_conv, cudaFuncAttributeMaxDynamicSharedMemorySize, K4T_SMEM);
        configured = 1;
    }

    k0_prep<<<105, 512>>>(conv_w);               // merged aprep + twiddles
    k1t_dft<<<BCn*Ln, 256, K1T_SMEM>>>(x);       // 4096 blocks, tensor DFT
    k2_ldft<<<BCn*4, 448>>>(x);
    k3_calib<<<BLn, 64>>>(temporal_w, temporal_b, fc_w, fc_b, conv_b);
    k4t_conv<<<dim3(TILES, BLn), 448, K4T_SMEM>>>(x, conv_w);
    k4b_stats<<<Cn, 256>>>();
    k5_bnsilu<<<NTOT/1024, 256>>>(bn_gamma, bn_beta, out);
}

// round 14
// speedup vs baseline: 1.2500x; 1.1700x over previous
#include <cuda_runtime.h>
#include <cuda_fp16.h>
#include <math.h>
#include <stdint.h>

#define Bn 8
#define Ln 8
#define Cn 64
#define Hn 56
#define Wn 56
#define HWn 3136
#define BCn (Bn*Cn)        // 512
#define BLn (Bn*Ln)        // 64
#define NTOT (BLn*Cn*HWn)  // 12,845,056
#define KWC 29             // compact kw count (Hermitian half)
#define NPOS (56*KWC)      // 1624 positions per slab
#define TILES 28           // k4t: 2 output rows per tile
#define NBLK (BLn*TILES)   // 1792 BN-partial slots

__device__ __forceinline__ uint32_t f2tf32(float v) {
    uint32_t b;
    asm("cvt.rna.tf32.f32 %0, %1;" : "=r"(b) : "f"(v));
    return b;
}
__device__ __forceinline__ void mma_tf32(float* d, const uint32_t* a, const uint32_t* b) {
    asm volatile(
        "mma.sync.aligned.m16n8k8.row.col.f32.tf32.tf32.f32 "
        "{%0,%1,%2,%3}, {%4,%5,%6,%7}, {%8,%9}, {%0,%1,%2,%3};\n"
        : "+f"(d[0]), "+f"(d[1]), "+f"(d[2]), "+f"(d[3])
        : "r"(a[0]), "r"(a[1]), "r"(a[2]), "r"(a[3]), "r"(b[0]), "r"(b[1]));
}

// ---------------- scratch (device globals; no runtime allocation) ----------
__device__ float  g_F2re[BCn*Ln*NPOS];  // compact 2D-DFT real plane (~26.6MB)
__device__ float  g_F2im[BCn*Ln*NPOS];  // compact 2D-DFT imag plane
__device__ __half g_yh[NTOT];           // pre-BN conv output, fp16 (~25.7MB)
__device__ float  g_ppart[BCn*4*Ln];    // pooled partials
__device__ float  g_s[BLn*Cn];          // per (b,l,ci) input-channel scale
__device__ float  g_fb[BLn*Cn];         // per (b,l,co) dynamic bias
__device__ __align__(16) uint32_t g_Atf[72*512];  // tf32 conv weights, swizzled
__device__ uint32_t g_WB[64*64];        // tf32 stage-B twiddles
__device__ uint32_t g_WC[112*112];      // tf32 stage-C twiddles [[C,-S],[S,C]]
__device__ float  g_bnsum2[Cn*NBLK];
__device__ float  g_bnsq2[Cn*NBLK];
__device__ float  g_mean[Cn];
__device__ float  g_invstd[Cn];

// ============================================================================
// K0: merged one-shot prep: conv-A tf32 (swizzled) + DFT twiddles tf32.
// ============================================================================
__global__ __launch_bounds__(512) void k0_prep(const float* __restrict__ convw) {
    int e = blockIdx.x*512 + threadIdx.x;
    const float TWO_PI = 6.28318530717958647692f;
    if (e < 36864) {
        int j  = e & 1;  int t = e >> 1;
        int tg = t & 3;  t >>= 2;
        int co = t & 63; int kkg = t >> 6;      // 0..71
        int k  = kkg*8 + tg + 4*j;
        int ci = k / 9, tap = k - 9*ci;
        g_Atf[kkg*512 + co*8 + ((tg ^ (co & 3)) << 1) + j] =
            f2tf32(convw[(co*64 + ci)*9 + tap]);
    } else if (e < 36864 + 4096) {
        int idx = e - 36864;
        int r = idx >> 6, cc = idx & 63;
        float v = 0.f;
        if (r < 56) {
            int kw = cc & 31;
            float ang = -TWO_PI * (float)((r*kw) % 56) / 56.f;
            float sv, cv; sincosf(ang, &sv, &cv);
            v = (cc < 32) ? cv : sv;
        }
        g_WB[idx] = f2tf32(v);
    } else if (e < 36864 + 4096 + 12544) {
        int e2 = e - 36864 - 4096;
        int r = e2 / 112, k = e2 % 112;
        int rr = (r < 56) ? r : r - 56;
        int kk = (k < 56) ? k : k - 56;
        float ang = -TWO_PI * (float)((rr*kk) % 56) / 56.f;
        float sv, cv; sincosf(ang, &sv, &cv);
        float v;
        if (r < 56) v = (k < 56) ? cv : -sv;
        else        v = (k < 56) ? sv : cv;
        g_WC[e2] = f2tf32(v);
    }
}

// ============================================================================
// K1T v2: tensor-core 2D DFT per slab. Twiddle fragments read DIRECTLY from
// global (L1-resident, 66KB) -> no per-block staging of constants; smem is
// only Xs + T1s = 32,000 B -> 5+ blocks/SM (was 2 at 100KB).
// ============================================================================
#define K1T_SMEM (8000*4)

__global__ __launch_bounds__(256, 4) void k1t_dft(const float* __restrict__ x) {
    extern __shared__ uint32_t sm1[];
    uint32_t* Xs  = sm1;            // 64*57  = 3648
    uint32_t* T1s = sm1 + 3648;     // 64*68  = 4352

    int slab = blockIdx.x;          // bc*8 + l
    int bc = slab >> 3, l = slab & 7;
    int b = bc >> 6, c = bc & 63;
    int tid = threadIdx.x;
    int wrp = tid >> 5, lane = tid & 31;
    int g = lane >> 2, tg = lane & 3;

    const float* xp = x + (size_t)((b*Ln + l)*Cn + c) * HWn;

    for (int e = tid; e < 3648; e += 256) Xs[e] = 0u;
    __syncthreads();
    for (int e = tid; e < 3136; e += 256) {
        int h = e / 56, ww = e % 56;
        Xs[h*57 + ww] = f2tf32(xp[e]);
    }
    __syncthreads();

    // ---- Stage B: T1(64x64) = Xs(64x56) @ WB(56x64); WB fragments via LDG
    {
        int mt = wrp & 3;
        int ng = (wrp >> 2) * 4;
        float accB[4][4];
        #pragma unroll
        for (int i = 0; i < 4; ++i)
            #pragma unroll
            for (int j = 0; j < 4; ++j) accB[i][j] = 0.f;

        for (int k = 0; k < 7; ++k) {
            int ab = (mt*16 + g)*57 + k*8 + tg;
            uint32_t a[4];
            a[0] = Xs[ab];            a[1] = Xs[ab + 8*57];
            a[2] = Xs[ab + 4];        a[3] = Xs[ab + 8*57 + 4];
            int kb0 = (k*8 + tg)*64;
            int kb1 = (k*8 + tg + 4)*64;
            #pragma unroll
            for (int i = 0; i < 4; ++i) {
                int ncol = (ng + i)*8 + g;
                uint32_t bfr[2] = { __ldg(&g_WB[kb0 + ncol]), __ldg(&g_WB[kb1 + ncol]) };
                mma_tf32(accB[i], a, bfr);
            }
        }
        #pragma unroll
        for (int i = 0; i < 4; ++i)
            #pragma unroll
            for (int j = 0; j < 4; ++j) {
                int row = mt*16 + g + (j >> 1)*8;
                int col = (ng + i)*8 + tg*2 + (j & 1);
                T1s[row*68 + col] = f2tf32(accB[i][j]);
            }
    }
    __syncthreads();

    // ---- Stage C: T2(112x32) = WC(112x112) @ [T1re;T1im]; WC via LDG
    float* re = g_F2re + (size_t)slab * NPOS;
    float* im = g_F2im + (size_t)slab * NPOS;
    for (int u = wrp; u < 14; u += 8) {
        int mt = u >> 1, nh = u & 1;
        float accC[2][4];
        #pragma unroll
        for (int i = 0; i < 2; ++i)
            #pragma unroll
            for (int j = 0; j < 4; ++j) accC[i][j] = 0.f;

        for (int k = 0; k < 14; ++k) {
            int ab = (mt*16 + g)*112 + k*8 + tg;
            uint32_t a[4];
            a[0] = __ldg(&g_WC[ab]);            a[1] = __ldg(&g_WC[ab + 8*112]);
            a[2] = __ldg(&g_WC[ab + 4]);        a[3] = __ldg(&g_WC[ab + 8*112 + 4]);
            int off  = (k >= 7) ? 56 : 0;
            int coff = (k >= 7) ? 32 : 0;
            int hr = k*8 + tg - off;
            #pragma unroll
            for (int i = 0; i < 2; ++i) {
                int ncol = (nh*2 + i)*8 + g + coff;
                uint32_t bfr[2] = { T1s[hr*68 + ncol], T1s[(hr + 4)*68 + ncol] };
                mma_tf32(accC[i], a, bfr);
            }
        }
        #pragma unroll
        for (int i = 0; i < 2; ++i) {
            int nt = nh*2 + i;
            #pragma unroll
            for (int j = 0; j < 4; ++j) {
                int r  = mt*16 + g + (j >> 1)*8;
                int kw = nt*8 + tg*2 + (j & 1);
                if (kw <= 28) {
                    if (r < 56) re[r*KWC + kw] = accC[i][j];
                    else        im[(r - 56)*KWC + kw] = accC[i][j];
                }
            }
        }
    }
}

// ============================================================================
// K2: 8-point DFT along L + magnitude; mirror reuse. (unchanged)
// ============================================================================
__global__ __launch_bounds__(448) void k2_ldft(const float* __restrict__ x) {
    int bx = blockIdx.x;
    int bc = bx >> 2, jb = bx & 3;
    int b  = bc >> 6, c = bc & 63;
    int tid = threadIdx.x;
    int idx = jb * 448 + tid;

    float contrib[8];
    #pragma unroll
    for (int k = 0; k < 8; ++k) contrib[k] = 0.f;

    if (idx < NPOS) {
        int kh = idx / KWC, kw = idx % KWC;
        int p  = kh*56 + kw;
        int pm = ((56 - kh) % 56)*56 + ((56 - kw) % 56);
        bool do_m = (kw >= 1 && kw <= 27);

        const float* f2r = g_F2re + (size_t)(bc*Ln) * NPOS + idx;
        const float* f2i = g_F2im + (size_t)(bc*Ln) * NPOS + idx;
        float fr[8], fi[8];
        #pragma unroll
        for (int l2 = 0; l2 < 8; ++l2) {
            fr[l2] = f2r[(size_t)l2 * NPOS];
            fi[l2] = f2i[(size_t)l2 * NPOS];
        }

        const float RT = 0.70710678118654752f;
        const float twc[8] = {1.f,  RT, 0.f, -RT, -1.f, -RT, 0.f,  RT};
        const float tws[8] = {0.f, -RT, -1.f, -RT, 0.f,  RT, 1.f,  RT};
        const float SCALE = 0.01f / 158.39507568359375f;

        float mag[8];
        #pragma unroll
        for (int k = 0; k < 8; ++k) {
            float re = 0.f, im = 0.f;
            #pragma unroll
            for (int l2 = 0; l2 < 8; ++l2) {
                int j = (l2 * k) & 7;
                re += twc[j]*fr[l2] - tws[j]*fi[l2];
                im += twc[j]*fi[l2] + tws[j]*fr[l2];
            }
            mag[k] = sqrtf(re*re + im*im);
        }

        #pragma unroll
        for (int k = 0; k < 8; ++k) {
            const float* xl = x + (size_t)((b*Ln + k)*Cn + c) * HWn;
            float v = xl[p] * (1.0f + SCALE * mag[k]);
            if (do_m)
                v += xl[pm] * (1.0f + SCALE * mag[(8 - k) & 7]);
            contrib[k] = v;
        }
    }

    #pragma unroll
    for (int k = 0; k < 8; ++k)
        #pragma unroll
        for (int off = 16; off > 0; off >>= 1)
            contrib[k] += __shfl_down_sync(0xffffffff, contrib[k], off);

    __shared__ float ws[14][8];
    int wid = tid >> 5, lane = tid & 31;
    if (lane == 0) {
        #pragma unroll
        for (int k = 0; k < 8; ++k) ws[wid][k] = contrib[k];
    }
    __syncthreads();
    if (tid < 8) {
        float s = 0.f;
        #pragma unroll
        for (int w2 = 0; w2 < 14; ++w2) s += ws[w2][tid];
        g_ppart[(bc*4 + jb)*8 + tid] = s;
    }
}

// ============================================================================
// K3: pooled -> calibration. (unchanged)
// ============================================================================
__global__ __launch_bounds__(64) void k3_calib(
    const float* __restrict__ tw_, const float* __restrict__ tb,
    const float* __restrict__ fcw, const float* __restrict__ fcb,
    const float* __restrict__ convb)
{
    int bl = blockIdx.x;
    int b  = bl >> 3, l = bl & 7;
    int tid = threadIdx.x;

    __shared__ float pooled[64];
    __shared__ float fcp[65];

    float s = 0.f;
    #pragma unroll
    for (int j = 0; j < 4; ++j)
        s += g_ppart[((b*Cn + tid)*4 + j)*8 + l];
    float pv = s * (1.0f / 3136.0f);
    pooled[tid] = pv;
    fcp[tid] = fcw[tid] * pv;
    __syncthreads();

    float calib = tb[tid];
    #pragma unroll 8
    for (int c = 0; c < 64; ++c) calib += tw_[tid*64 + c] * pooled[c];
    g_s[bl*Cn + tid] = calib + 1.0f;

    if (tid == 0) {
        float f = fcb[0];
        for (int c = 0; c < 64; ++c) f += fcp[c];
        fcp[64] = f + 1.0f;
    }
    __syncthreads();
    g_fb[bl*Cn + tid] = convb[tid] * fcp[64];
}

// ============================================================================
// K4T: tf32 implicit-GEMM conv (unchanged from R13: fp16 y stores).
// ============================================================================
#define K4T_SMEM ((15360 + 9216 + 576) * 4)   // 100,608 B

__global__ __launch_bounds__(448, 2) void k4t_conv(const float* __restrict__ x,
                                                   const float* __restrict__ convw) {
    extern __shared__ uint32_t dsm[];
    uint32_t* xs   = dsm;                   // 15360 u32: [64ci][4r][60]
    uint32_t* As   = dsm + 15360;           // 9216 u32
    uint32_t* kOff = dsm + 15360 + 9216;    // 576 u32
    __shared__ float ssh[64];
    __shared__ float red_s[14][32];
    __shared__ float red_q[14][32];

    int tile = blockIdx.x;   // 0..27
    int bl   = blockIdx.y;   // 0..63
    int tid  = threadIdx.x;
    int w    = tid >> 5;
    int lane = tid & 31;
    int g    = lane >> 2;    // 0..7
    int tg   = lane & 3;     // 0..3
    int mw   = w & 1;
    int nw   = w >> 1;       // 0..6
    int mwbase = mw * 32;

    if (tid < 64) ssh[tid] = g_s[bl*64 + tid];
    for (int k = tid; k < 576; k += 448) {
        int ci = k / 9, tap = k - 9*ci, dr = tap / 3, dc = tap - 3*dr;
        kOff[k] = (uint32_t)(ci*240 + dr*60 + dc);
    }
    __syncthreads();

    const float* xb = x + (size_t)bl * 64 * HWn;
    for (int e = tid; e < 64*4*58; e += 448) {
        int c = e % 58; int t = e / 58; int r = t & 3; int ci = t >> 2;
        int gr = 2*tile - 1 + r; int gc = c - 1;
        float v = 0.f;
        if (gr >= 0 && gr < 56 && gc >= 0 && gc < 56)
            v = xb[ci*HWn + gr*56 + gc] * ssh[ci];
        xs[ci*240 + r*60 + c] = f2tf32(v);
    }

    uint32_t pxoff[2];
    #pragma unroll
    for (int nf = 0; nf < 2; ++nf) {
        int px = nw*16 + nf*8 + g;
        int rs = (px >= 56) ? 1 : 0;
        pxoff[nf] = (uint32_t)(rs*60 + (px - rs*56));
    }
    int swz = ((tg ^ (g & 3)) << 1);

    float acc[2][2][4];
    #pragma unroll
    for (int mf = 0; mf < 2; ++mf)
        #pragma unroll
        for (int nf = 0; nf < 2; ++nf)
            #pragma unroll
            for (int j = 0; j < 4; ++j) acc[mf][nf][j] = 0.f;

    for (int q = 0; q < 4; ++q) {
        __syncthreads();
        {
            const uint4* srcv = (const uint4*)(g_Atf + q*9216);
            uint4* dstv = (uint4*)As;
            for (int e = tid; e < 2304; e += 448) dstv[e] = srcv[e];
        }
        __syncthreads();

        int kbase = q*144;
        #pragma unroll 2
        for (int kk = 0; kk < 18; ++kk) {
            uint32_t ko0 = kOff[kbase + kk*8 + tg];
            uint32_t ko4 = kOff[kbase + kk*8 + tg + 4];

            uint32_t a[2][4];
            #pragma unroll
            for (int mf = 0; mf < 2; ++mf) {
                const uint32_t* base0 = As + kk*512 + (mwbase + mf*16 + g)*8 + swz;
                uint2 p0 = *(const uint2*)base0;
                uint2 p1 = *(const uint2*)(base0 + 64);
                a[mf][0] = p0.x; a[mf][1] = p1.x; a[mf][2] = p0.y; a[mf][3] = p1.y;
            }
            uint32_t b[2][2];
            #pragma unroll
            for (int nf = 0; nf < 2; ++nf) {
                b[nf][0] = xs[ko0 + pxoff[nf]];
                b[nf][1] = xs[ko4 + pxoff[nf]];
            }
            #pragma unroll
            for (int mf = 0; mf < 2; ++mf)
                #pragma unroll
                for (int nf = 0; nf < 2; ++nf)
                    mma_tf32(acc[mf][nf], a[mf], b[nf]);
        }
    }
    __syncthreads();

    // ---- epilogue: + fb + residual, half2-packed y stores, BN partials ----
    float psum[2][2] = {{0.f,0.f},{0.f,0.f}};
    float psq [2][2] = {{0.f,0.f},{0.f,0.f}};
    #pragma unroll
    for (int mf = 0; mf < 2; ++mf) {
        #pragma unroll
        for (int nf = 0; nf < 2; ++nf) {
            #pragma unroll
            for (int hi = 0; hi < 2; ++hi) {
                int co = mwbase + mf*16 + g + hi*8;
                float fbv = g_fb[bl*64 + co];
                int px0 = nw*16 + nf*8 + tg*2;
                int rs = (px0 >= 56) ? 1 : 0;
                int row = 2*tile + rs;
                int col = px0 - rs*56;
                int loc = co*HWn + row*56 + col;
                float v0 = acc[mf][nf][hi*2 + 0] + fbv + xb[loc];
                float v1 = acc[mf][nf][hi*2 + 1] + fbv + xb[loc + 1];
                __half2 h2 = __floats2half2_rn(v0, v1);
                *(__half2*)(g_yh + (size_t)bl*64*HWn + loc) = h2;
                float r0 = __half2float(__low2half(h2));
                float r1 = __half2float(__high2half(h2));
                psum[mf][hi] += r0 + r1;
                psq [mf][hi] += r0*r0 + r1*r1;
            }
        }
    }
    #pragma unroll
    for (int mf = 0; mf < 2; ++mf)
        #pragma unroll
        for (int hi = 0; hi < 2; ++hi) {
            float s = psum[mf][hi], q = psq[mf][hi];
            s += __shfl_down_sync(0xffffffffu, s, 2, 4);
            s += __shfl_down_sync(0xffffffffu, s, 1, 4);
            q += __shfl_down_sync(0xffffffffu, q, 2, 4);
            q += __shfl_down_sync(0xffffffffu, q, 1, 4);
            if (tg == 0) {
                red_s[w][mf*16 + hi*8 + g] = s;
                red_q[w][mf*16 + hi*8 + g] = q;
            }
        }
    __syncthreads();
    if (tid < 64) {
        int co = tid;
        int mw2 = co >> 5; int rem = co & 31;
        int mf = rem >> 4; int g8 = rem & 15;
        int hi = g8 >> 3;  int g2 = g8 & 7;
        int idx = mf*16 + hi*8 + g2;
        float s = 0.f, q = 0.f;
        #pragma unroll
        for (int nw2 = 0; nw2 < 7; ++nw2) {
            s += red_s[nw2*2 + mw2][idx];
            q += red_q[nw2*2 + mw2][idx];
        }
        g_bnsum2[co*NBLK + bl*TILES + tile] = s;
        g_bnsq2 [co*NBLK + bl*TILES + tile] = q;
    }
}

// ============================================================================
// K4b: final BN statistics. (unchanged)
// ============================================================================
__global__ __launch_bounds__(256) void k4b_stats() {
    int co  = blockIdx.x;
    int tid = threadIdx.x;
    float s = 0.f, q = 0.f;
    for (int i = tid; i < NBLK; i += 256) {
        s += g_bnsum2[co*NBLK + i];
        q += g_bnsq2 [co*NBLK + i];
    }
    #pragma unroll
    for (int off = 16; off > 0; off >>= 1) {
        s += __shfl_down_sync(0xffffffffu, s, off);
        q += __shfl_down_sync(0xffffffffu, q, off);
    }
    __shared__ float ws2[8], wq2[8];
    int wid = tid >> 5, lane = tid & 31;
    if (lane == 0) { ws2[wid] = s; wq2[wid] = q; }
    __syncthreads();
    if (tid == 0) {
        float S = 0.f, Q = 0.f;
        #pragma unroll
        for (int i = 0; i < 8; ++i) { S += ws2[i]; Q += wq2[i]; }
        const float invN = 1.0f / (float)(BLn * HWn);
        float mean = S * invN;
        float var  = Q * invN - mean*mean;
        g_mean[co]   = mean;
        g_invstd[co] = rsqrtf(var + 1e-5f);
    }
}

// ============================================================================
// K5: BN normalize + affine + SiLU -> d_out; reads fp16 y. (unchanged)
// ============================================================================
__global__ __launch_bounds__(256) void k5_bnsilu(const float* __restrict__ gamma,
                                                 const float* __restrict__ beta,
                                                 float* __restrict__ out) {
    int i4 = blockIdx.x * 256 + threadIdx.x;
    int c = ((i4 * 4) / HWn) & 63;
    uint2 yv = ((const uint2*)g_yh)[i4];
    __half2 h01 = *(__half2*)&yv.x;
    __half2 h23 = *(__half2*)&yv.y;
    float2 f01 = __half22float2(h01);
    float2 f23 = __half22float2(h23);
    float m = g_mean[c], is = g_invstd[c] * gamma[c], bt = beta[c];
    float4 o;
    o.x = (f01.x - m) * is + bt;
    o.y = (f01.y - m) * is + bt;
    o.z = (f23.x - m) * is + bt;
    o.w = (f23.y - m) * is + bt;
    o.x = o.x / (1.0f + __expf(-o.x));
    o.y = o.y / (1.0f + __expf(-o.y));
    o.z = o.z / (1.0f + __expf(-o.z));
    o.w = o.w / (1.0f + __expf(-o.w));
    ((float4*)out)[i4] = o;
}

// ============================================================================
extern "C" void kernel_launch(void* const* d_in, const int* in_sizes, int n_in,
                              void* d_out, int out_size) {
    const float* x          = (const float*)d_in[0];
    const float* temporal_w = (const float*)d_in[1];
    const float* temporal_b = (const float*)d_in[2];
    const float* fc_w       = (const float*)d_in[3];
    const float* fc_b       = (const float*)d_in[4];
    const float* conv_w     = (const float*)d_in[5];
    const float* conv_b     = (const float*)d_in[6];
    const float* bn_gamma   = (const float*)d_in[7];
    const float* bn_beta    = (const float*)d_in[8];
    float* out = (float*)d_out;

    static int configured = 0;
    if (!configured) {
        cudaFuncSetAttribute(k1t_dft,  cudaFuncAttributeMaxDynamicSharedMemorySize, K1T_SMEM);
        cudaFuncSetAttribute(k4t_conv, cudaFuncAttributeMaxDynamicSharedMemorySize, K4T_SMEM);
        configured = 1;
    }

    k0_prep<<<105, 512>>>(conv_w);               // merged aprep + twiddles
    k1t_dft<<<BCn*Ln, 256, K1T_SMEM>>>(x);       // 4096 blocks, tensor DFT
    k2_ldft<<<BCn*4, 448>>>(x);
    k3_calib<<<BLn, 64>>>(temporal_w, temporal_b, fc_w, fc_b, conv_b);
    k4t_conv<<<dim3(TILES, BLn), 448, K4T_SMEM>>>(x, conv_w);
    k4b_stats<<<Cn, 256>>>();
    k5_bnsilu<<<NTOT/1024, 256>>>(bn_gamma, bn_beta, out);
}

// round 15
// speedup vs baseline: 1.6142x; 1.2914x over previous
#include <cuda_runtime.h>
#include <cuda_fp16.h>
#include <math.h>
#include <stdint.h>

#define Bn 8
#define Ln 8
#define Cn 64
#define Hn 56
#define Wn 56
#define HWn 3136
#define BCn (Bn*Cn)        // 512
#define BLn (Bn*Ln)        // 64
#define NTOT (BLn*Cn*HWn)  // 12,845,056
#define KWC 29             // compact kw count (Hermitian half)
#define NPOS (56*KWC)      // 1624 positions per slab
#define TILES 28           // k4t: 2 output rows per tile
#define NBLK (BLn*TILES)   // 1792 BN-partial slots

__device__ __forceinline__ uint32_t f2tf32(float v) {
    uint32_t b;
    asm("cvt.rna.tf32.f32 %0, %1;" : "=r"(b) : "f"(v));
    return b;
}
__device__ __forceinline__ void mma_tf32(float* d, const uint32_t* a, const uint32_t* b) {
    asm volatile(
        "mma.sync.aligned.m16n8k8.row.col.f32.tf32.tf32.f32 "
        "{%0,%1,%2,%3}, {%4,%5,%6,%7}, {%8,%9}, {%0,%1,%2,%3};\n"
        : "+f"(d[0]), "+f"(d[1]), "+f"(d[2]), "+f"(d[3])
        : "r"(a[0]), "r"(a[1]), "r"(a[2]), "r"(a[3]), "r"(b[0]), "r"(b[1]));
}
__device__ __forceinline__ void mma_f16(float* d, const uint32_t* a, const uint32_t* b) {
    asm volatile(
        "mma.sync.aligned.m16n8k16.row.col.f32.f16.f16.f32 "
        "{%0,%1,%2,%3}, {%4,%5,%6,%7}, {%8,%9}, {%0,%1,%2,%3};\n"
        : "+f"(d[0]), "+f"(d[1]), "+f"(d[2]), "+f"(d[3])
        : "r"(a[0]), "r"(a[1]), "r"(a[2]), "r"(a[3]), "r"(b[0]), "r"(b[1]));
}

// ---------------- scratch (device globals; no runtime allocation) ----------
__device__ float  g_F2re[BCn*Ln*NPOS];  // compact 2D-DFT real plane (~26.6MB)
__device__ float  g_F2im[BCn*Ln*NPOS];  // compact 2D-DFT imag plane
__device__ __half g_yh[NTOT];           // pre-BN conv output, fp16 (~25.7MB)
__device__ float  g_ppart[BCn*4*Ln];    // pooled partials
__device__ float  g_s[BLn*Cn];          // per (b,l,ci) input-channel scale
__device__ float  g_fb[BLn*Cn];         // per (b,l,co) dynamic bias
__device__ __align__(16) uint32_t g_Ah[36*512];   // fp16 conv weights [chunk][co][8]
__device__ uint32_t g_WB[64*64];        // tf32 stage-B twiddles
__device__ uint32_t g_WC[112*112];      // tf32 stage-C twiddles [[C,-S],[S,C]]
__device__ float  g_bnsum2[Cn*NBLK];
__device__ float  g_bnsq2[Cn*NBLK];
__device__ float  g_mean[Cn];
__device__ float  g_invstd[Cn];

// ============================================================================
// K0: merged one-shot prep: conv-A fp16 fragments (tap-major k) + twiddles.
// A layout: k = tap*64 + ci; chunk c (16 k) -> tap = c>>2, ci0 = (c&3)*16.
// g_Ah[(c*64+co)*8 + p], p = 2t+j: half2 of k-halves (ci0+2t+8j, +1).
// ============================================================================
__global__ __launch_bounds__(512) void k0_prep(const float* __restrict__ convw) {
    int e = blockIdx.x*512 + threadIdx.x;
    const float TWO_PI = 6.28318530717958647692f;
    if (e < 18432) {
        int c  = e >> 9;
        int r9 = e & 511;
        int co = r9 >> 3;
        int p  = r9 & 7;
        int t  = p >> 1, j = p & 1;
        int kidx = 2*t + 8*j;
        int ci  = (c & 3)*16 + kidx;
        int tap = c >> 2;
        float f0 = convw[(co*64 + ci    )*9 + tap];
        float f1 = convw[(co*64 + ci + 1)*9 + tap];
        __half2 h2 = __floats2half2_rn(f0, f1);
        g_Ah[e] = *(uint32_t*)&h2;
    } else if (e < 18432 + 4096) {
        int idx = e - 18432;
        int r = idx >> 6, cc = idx & 63;
        float v = 0.f;
        if (r < 56) {
            int kw = cc & 31;
            float ang = -TWO_PI * (float)((r*kw) % 56) / 56.f;
            float sv, cv; sincosf(ang, &sv, &cv);
            v = (cc < 32) ? cv : sv;
        }
        g_WB[idx] = f2tf32(v);
    } else if (e < 18432 + 4096 + 12544) {
        int e2 = e - 18432 - 4096;
        int r = e2 / 112, k = e2 % 112;
        int rr = (r < 56) ? r : r - 56;
        int kk = (k < 56) ? k : k - 56;
        float ang = -TWO_PI * (float)((rr*kk) % 56) / 56.f;
        float sv, cv; sincosf(ang, &sv, &cv);
        float v;
        if (r < 56) v = (k < 56) ? cv : -sv;
        else        v = (k < 56) ? sv : cv;
        g_WC[e2] = f2tf32(v);
    }
}

// ============================================================================
// K1T: tensor-core 2D DFT per slab; twiddles via L1-resident LDG.
// (unchanged from R14 winner)
// ============================================================================
#define K1T_SMEM (8000*4)

__global__ __launch_bounds__(256, 4) void k1t_dft(const float* __restrict__ x) {
    extern __shared__ uint32_t sm1[];
    uint32_t* Xs  = sm1;            // 64*57  = 3648
    uint32_t* T1s = sm1 + 3648;     // 64*68  = 4352

    int slab = blockIdx.x;          // bc*8 + l
    int bc = slab >> 3, l = slab & 7;
    int b = bc >> 6, c = bc & 63;
    int tid = threadIdx.x;
    int wrp = tid >> 5, lane = tid & 31;
    int g = lane >> 2, tg = lane & 3;

    const float* xp = x + (size_t)((b*Ln + l)*Cn + c) * HWn;

    for (int e = tid; e < 3648; e += 256) Xs[e] = 0u;
    __syncthreads();
    for (int e = tid; e < 3136; e += 256) {
        int h = e / 56, ww = e % 56;
        Xs[h*57 + ww] = f2tf32(xp[e]);
    }
    __syncthreads();

    // ---- Stage B
    {
        int mt = wrp & 3;
        int ng = (wrp >> 2) * 4;
        float accB[4][4];
        #pragma unroll
        for (int i = 0; i < 4; ++i)
            #pragma unroll
            for (int j = 0; j < 4; ++j) accB[i][j] = 0.f;

        for (int k = 0; k < 7; ++k) {
            int ab = (mt*16 + g)*57 + k*8 + tg;
            uint32_t a[4];
            a[0] = Xs[ab];            a[1] = Xs[ab + 8*57];
            a[2] = Xs[ab + 4];        a[3] = Xs[ab + 8*57 + 4];
            int kb0 = (k*8 + tg)*64;
            int kb1 = (k*8 + tg + 4)*64;
            #pragma unroll
            for (int i = 0; i < 4; ++i) {
                int ncol = (ng + i)*8 + g;
                uint32_t bfr[2] = { __ldg(&g_WB[kb0 + ncol]), __ldg(&g_WB[kb1 + ncol]) };
                mma_tf32(accB[i], a, bfr);
            }
        }
        #pragma unroll
        for (int i = 0; i < 4; ++i)
            #pragma unroll
            for (int j = 0; j < 4; ++j) {
                int row = mt*16 + g + (j >> 1)*8;
                int col = (ng + i)*8 + tg*2 + (j & 1);
                T1s[row*68 + col] = f2tf32(accB[i][j]);
            }
    }
    __syncthreads();

    // ---- Stage C
    float* re = g_F2re + (size_t)slab * NPOS;
    float* im = g_F2im + (size_t)slab * NPOS;
    for (int u = wrp; u < 14; u += 8) {
        int mt = u >> 1, nh = u & 1;
        float accC[2][4];
        #pragma unroll
        for (int i = 0; i < 2; ++i)
            #pragma unroll
            for (int j = 0; j < 4; ++j) accC[i][j] = 0.f;

        for (int k = 0; k < 14; ++k) {
            int ab = (mt*16 + g)*112 + k*8 + tg;
            uint32_t a[4];
            a[0] = __ldg(&g_WC[ab]);            a[1] = __ldg(&g_WC[ab + 8*112]);
            a[2] = __ldg(&g_WC[ab + 4]);        a[3] = __ldg(&g_WC[ab + 8*112 + 4]);
            int off  = (k >= 7) ? 56 : 0;
            int coff = (k >= 7) ? 32 : 0;
            int hr = k*8 + tg - off;
            #pragma unroll
            for (int i = 0; i < 2; ++i) {
                int ncol = (nh*2 + i)*8 + g + coff;
                uint32_t bfr[2] = { T1s[hr*68 + ncol], T1s[(hr + 4)*68 + ncol] };
                mma_tf32(accC[i], a, bfr);
            }
        }
        #pragma unroll
        for (int i = 0; i < 2; ++i) {
            int nt = nh*2 + i;
            #pragma unroll
            for (int j = 0; j < 4; ++j) {
                int r  = mt*16 + g + (j >> 1)*8;
                int kw = nt*8 + tg*2 + (j & 1);
                if (kw <= 28) {
                    if (r < 56) re[r*KWC + kw] = accC[i][j];
                    else        im[(r - 56)*KWC + kw] = accC[i][j];
                }
            }
        }
    }
}

// ============================================================================
// K2: 8-point DFT along L + magnitude; mirror reuse. (unchanged)
// ============================================================================
__global__ __launch_bounds__(448) void k2_ldft(const float* __restrict__ x) {
    int bx = blockIdx.x;
    int bc = bx >> 2, jb = bx & 3;
    int b  = bc >> 6, c = bc & 63;
    int tid = threadIdx.x;
    int idx = jb * 448 + tid;

    float contrib[8];
    #pragma unroll
    for (int k = 0; k < 8; ++k) contrib[k] = 0.f;

    if (idx < NPOS) {
        int kh = idx / KWC, kw = idx % KWC;
        int p  = kh*56 + kw;
        int pm = ((56 - kh) % 56)*56 + ((56 - kw) % 56);
        bool do_m = (kw >= 1 && kw <= 27);

        const float* f2r = g_F2re + (size_t)(bc*Ln) * NPOS + idx;
        const float* f2i = g_F2im + (size_t)(bc*Ln) * NPOS + idx;
        float fr[8], fi[8];
        #pragma unroll
        for (int l2 = 0; l2 < 8; ++l2) {
            fr[l2] = f2r[(size_t)l2 * NPOS];
            fi[l2] = f2i[(size_t)l2 * NPOS];
        }

        const float RT = 0.70710678118654752f;
        const float twc[8] = {1.f,  RT, 0.f, -RT, -1.f, -RT, 0.f,  RT};
        const float tws[8] = {0.f, -RT, -1.f, -RT, 0.f,  RT, 1.f,  RT};
        const float SCALE = 0.01f / 158.39507568359375f;

        float mag[8];
        #pragma unroll
        for (int k = 0; k < 8; ++k) {
            float re = 0.f, im = 0.f;
            #pragma unroll
            for (int l2 = 0; l2 < 8; ++l2) {
                int j = (l2 * k) & 7;
                re += twc[j]*fr[l2] - tws[j]*fi[l2];
                im += twc[j]*fi[l2] + tws[j]*fr[l2];
            }
            mag[k] = sqrtf(re*re + im*im);
        }

        #pragma unroll
        for (int k = 0; k < 8; ++k) {
            const float* xl = x + (size_t)((b*Ln + k)*Cn + c) * HWn;
            float v = xl[p] * (1.0f + SCALE * mag[k]);
            if (do_m)
                v += xl[pm] * (1.0f + SCALE * mag[(8 - k) & 7]);
            contrib[k] = v;
        }
    }

    #pragma unroll
    for (int k = 0; k < 8; ++k)
        #pragma unroll
        for (int off = 16; off > 0; off >>= 1)
            contrib[k] += __shfl_down_sync(0xffffffff, contrib[k], off);

    __shared__ float ws[14][8];
    int wid = tid >> 5, lane = tid & 31;
    if (lane == 0) {
        #pragma unroll
        for (int k = 0; k < 8; ++k) ws[wid][k] = contrib[k];
    }
    __syncthreads();
    if (tid < 8) {
        float s = 0.f;
        #pragma unroll
        for (int w2 = 0; w2 < 14; ++w2) s += ws[w2][tid];
        g_ppart[(bc*4 + jb)*8 + tid] = s;
    }
}

// ============================================================================
// K3: pooled -> calibration. (unchanged)
// ============================================================================
__global__ __launch_bounds__(64) void k3_calib(
    const float* __restrict__ tw_, const float* __restrict__ tb,
    const float* __restrict__ fcw, const float* __restrict__ fcb,
    const float* __restrict__ convb)
{
    int bl = blockIdx.x;
    int b  = bl >> 3, l = bl & 7;
    int tid = threadIdx.x;

    __shared__ float pooled[64];
    __shared__ float fcp[65];

    float s = 0.f;
    #pragma unroll
    for (int j = 0; j < 4; ++j)
        s += g_ppart[((b*Cn + tid)*4 + j)*8 + l];
    float pv = s * (1.0f / 3136.0f);
    pooled[tid] = pv;
    fcp[tid] = fcw[tid] * pv;
    __syncthreads();

    float calib = tb[tid];
    #pragma unroll 8
    for (int c = 0; c < 64; ++c) calib += tw_[tid*64 + c] * pooled[c];
    g_s[bl*Cn + tid] = calib + 1.0f;

    if (tid == 0) {
        float f = fcb[0];
        for (int c = 0; c < 64; ++c) f += fcp[c];
        fcp[64] = f + 1.0f;
    }
    __syncthreads();
    g_fb[bl*Cn + tid] = convb[tid] * fcp[64];
}

// ============================================================================
// K4T v4: fp16 implicit-GEMM conv via mma.m16n8k16.
//  - k remapped tap-major (k = tap*64 + ci): each 16-k chunk has ONE tap and
//    16 consecutive ci -> B fragments are natively-packed half2 LDS.32.
//  - A (weights) fp16, pre-fragmented in g_Ah; read via L1-resident LDG.64.
//  - xs: [4r][58px][72 ci-pitch] halves (pitch 36 words = 4 mod 32 -> b-load
//    banks 4g+tg all distinct). smem 33,408 B. Scale s folded into xs.
//  - ONE barrier after staging; 36-chunk unrolled mainloop; fp32 accum.
// ============================================================================
#define K4T_SMEM (16704*2)   // 33,408 B

__global__ __launch_bounds__(448, 2) void k4t_conv(const float* __restrict__ x,
                                                   const float* __restrict__ convw) {
    extern __shared__ uint32_t xs32[];      // 8352 u32 = [4][58][36 words]
    __shared__ float ssh[64];
    __shared__ float red_s[14][32];
    __shared__ float red_q[14][32];

    int tile = blockIdx.x;   // 0..27
    int bl   = blockIdx.y;   // 0..63
    int tid  = threadIdx.x;
    int w    = tid >> 5;
    int lane = tid & 31;
    int g    = lane >> 2;    // 0..7
    int tg   = lane & 3;     // 0..3
    int mw   = w & 1;
    int nw   = w >> 1;       // 0..6
    int mwbase = mw * 32;

    if (tid < 64) ssh[tid] = g_s[bl*64 + tid];
    __syncthreads();

    const float* xb = x + (size_t)bl * 64 * HWn;

    // ---- stage x tile as fp16 (scale folded). Warp = 8 cols x 4 ci-pairs:
    // store banks 4*c8 + p -> conflict-free half2 stores.
    for (int wi = w; wi < 256; wi += 14) {
        int cb  = wi & 7;
        int r   = (wi >> 3) & 3;
        int cip = wi >> 5;              // 0..7
        int c   = cb*8 + (lane & 7);    // 0..63 (valid < 58)
        int p   = cip*4 + (lane >> 3);  // ci-pair 0..31
        if (c < 58) {
            int gr = 2*tile - 1 + r;
            int gc = c - 1;
            float v0 = 0.f, v1 = 0.f;
            if (gr >= 0 && gr < 56 && gc >= 0 && gc < 56) {
                int ci = p*2;
                int off = gr*56 + gc;
                v0 = xb[(size_t)ci*HWn + off] * ssh[ci];
                v1 = xb[(size_t)(ci+1)*HWn + off] * ssh[ci+1];
            }
            __half2 h2 = __floats2half2_rn(v0, v1);
            xs32[(r*58 + c)*36 + p] = *(uint32_t*)&h2;
        }
    }
    __syncthreads();

    // per-nf column/row-split (uniform within each 8-px group since 56 = 7*8)
    int colb[2], rsv[2];
    #pragma unroll
    for (int nf = 0; nf < 2; ++nf) {
        int px = nw*16 + nf*8 + g;
        int rs = (px >= 56) ? 1 : 0;
        rsv[nf]  = rs;
        colb[nf] = px - rs*56;
    }

    float acc[2][2][4];
    #pragma unroll
    for (int mf = 0; mf < 2; ++mf)
        #pragma unroll
        for (int nf = 0; nf < 2; ++nf)
            #pragma unroll
            for (int j = 0; j < 4; ++j) acc[mf][nf][j] = 0.f;

    int aoff0 = (mwbase + g)*8 + 2*tg;          // mf=0 row-g fragment offset
    #pragma unroll
    for (int dr = 0; dr < 3; ++dr) {
        #pragma unroll
        for (int dc2 = 0; dc2 < 3; ++dc2) {
            int tap = dr*3 + dc2;
            #pragma unroll
            for (int q = 0; q < 4; ++q) {
                const uint32_t* ab = g_Ah + (tap*4 + q)*512;
                uint32_t a[2][4];
                #pragma unroll
                for (int mf = 0; mf < 2; ++mf) {
                    uint2 p0 = __ldg((const uint2*)(ab + aoff0 + mf*128));        // rows g
                    uint2 p1 = __ldg((const uint2*)(ab + aoff0 + mf*128 + 64));   // rows g+8
                    a[mf][0] = p0.x; a[mf][1] = p1.x; a[mf][2] = p0.y; a[mf][3] = p1.y;
                }
                uint32_t b[2][2];
                #pragma unroll
                for (int nf = 0; nf < 2; ++nf) {
                    int widx = ((rsv[nf] + dr)*58 + colb[nf] + dc2)*36 + q*8 + tg;
                    b[nf][0] = xs32[widx];
                    b[nf][1] = xs32[widx + 4];
                }
                #pragma unroll
                for (int mf = 0; mf < 2; ++mf)
                    #pragma unroll
                    for (int nf = 0; nf < 2; ++nf)
                        mma_f16(acc[mf][nf], a[mf], b[nf]);
            }
        }
    }

    // ---- epilogue: + fb + residual, half2-packed y stores, BN partials ----
    float psum[2][2] = {{0.f,0.f},{0.f,0.f}};
    float psq [2][2] = {{0.f,0.f},{0.f,0.f}};
    #pragma unroll
    for (int mf = 0; mf < 2; ++mf) {
        #pragma unroll
        for (int nf = 0; nf < 2; ++nf) {
            #pragma unroll
            for (int hi = 0; hi < 2; ++hi) {
                int co = mwbase + mf*16 + g + hi*8;
                float fbv = g_fb[bl*64 + co];
                int px0 = nw*16 + nf*8 + tg*2;
                int rs = (px0 >= 56) ? 1 : 0;
                int row = 2*tile + rs;
                int col = px0 - rs*56;
                int loc = co*HWn + row*56 + col;
                float v0 = acc[mf][nf][hi*2 + 0] + fbv + xb[loc];
                float v1 = acc[mf][nf][hi*2 + 1] + fbv + xb[loc + 1];
                __half2 h2 = __floats2half2_rn(v0, v1);
                *(__half2*)(g_yh + (size_t)bl*64*HWn + loc) = h2;
                float r0 = __half2float(__low2half(h2));
                float r1 = __half2float(__high2half(h2));
                psum[mf][hi] += r0 + r1;
                psq [mf][hi] += r0*r0 + r1*r1;
            }
        }
    }
    #pragma unroll
    for (int mf = 0; mf < 2; ++mf)
        #pragma unroll
        for (int hi = 0; hi < 2; ++hi) {
            float s = psum[mf][hi], q = psq[mf][hi];
            s += __shfl_down_sync(0xffffffffu, s, 2, 4);
            s += __shfl_down_sync(0xffffffffu, s, 1, 4);
            q += __shfl_down_sync(0xffffffffu, q, 2, 4);
            q += __shfl_down_sync(0xffffffffu, q, 1, 4);
            if (tg == 0) {
                red_s[w][mf*16 + hi*8 + g] = s;
                red_q[w][mf*16 + hi*8 + g] = q;
            }
        }
    __syncthreads();
    if (tid < 64) {
        int co = tid;
        int mw2 = co >> 5; int rem = co & 31;
        int mf = rem >> 4; int g8 = rem & 15;
        int hi = g8 >> 3;  int g2 = g8 & 7;
        int idx = mf*16 + hi*8 + g2;
        float s = 0.f, q = 0.f;
        #pragma unroll
        for (int nw2 = 0; nw2 < 7; ++nw2) {
            s += red_s[nw2*2 + mw2][idx];
            q += red_q[nw2*2 + mw2][idx];
        }
        g_bnsum2[co*NBLK + bl*TILES + tile] = s;
        g_bnsq2 [co*NBLK + bl*TILES + tile] = q;
    }
}

// ============================================================================
// K4b: final BN statistics. (unchanged)
// ============================================================================
__global__ __launch_bounds__(256) void k4b_stats() {
    int co  = blockIdx.x;
    int tid = threadIdx.x;
    float s = 0.f, q = 0.f;
    for (int i = tid; i < NBLK; i += 256) {
        s += g_bnsum2[co*NBLK + i];
        q += g_bnsq2 [co*NBLK + i];
    }
    #pragma unroll
    for (int off = 16; off > 0; off >>= 1) {
        s += __shfl_down_sync(0xffffffffu, s, off);
        q += __shfl_down_sync(0xffffffffu, q, off);
    }
    __shared__ float ws2[8], wq2[8];
    int wid = tid >> 5, lane = tid & 31;
    if (lane == 0) { ws2[wid] = s; wq2[wid] = q; }
    __syncthreads();
    if (tid == 0) {
        float S = 0.f, Q = 0.f;
        #pragma unroll
        for (int i = 0; i < 8; ++i) { S += ws2[i]; Q += wq2[i]; }
        const float invN = 1.0f / (float)(BLn * HWn);
        float mean = S * invN;
        float var  = Q * invN - mean*mean;
        g_mean[co]   = mean;
        g_invstd[co] = rsqrtf(var + 1e-5f);
    }
}

// ============================================================================
// K5: BN normalize + affine + SiLU -> d_out; reads fp16 y. (unchanged)
// ============================================================================
__global__ __launch_bounds__(256) void k5_bnsilu(const float* __restrict__ gamma,
                                                 const float* __restrict__ beta,
                                                 float* __restrict__ out) {
    int i4 = blockIdx.x * 256 + threadIdx.x;
    int c = ((i4 * 4) / HWn) & 63;
    uint2 yv = ((const uint2*)g_yh)[i4];
    __half2 h01 = *(__half2*)&yv.x;
    __half2 h23 = *(__half2*)&yv.y;
    float2 f01 = __half22float2(h01);
    float2 f23 = __half22float2(h23);
    float m = g_mean[c], is = g_invstd[c] * gamma[c], bt = beta[c];
    float4 o;
    o.x = (f01.x - m) * is + bt;
    o.y = (f01.y - m) * is + bt;
    o.z = (f23.x - m) * is + bt;
    o.w = (f23.y - m) * is + bt;
    o.x = o.x / (1.0f + __expf(-o.x));
    o.y = o.y / (1.0f + __expf(-o.y));
    o.z = o.z / (1.0f + __expf(-o.z));
    o.w = o.w / (1.0f + __expf(-o.w));
    ((float4*)out)[i4] = o;
}

// ============================================================================
extern "C" void kernel_launch(void* const* d_in, const int* in_sizes, int n_in,
                              void* d_out, int out_size) {
    const float* x          = (const float*)d_in[0];
    const float* temporal_w = (const float*)d_in[1];
    const float* temporal_b = (const float*)d_in[2];
    const float* fc_w       = (const float*)d_in[3];
    const float* fc_b       = (const float*)d_in[4];
    const float* conv_w     = (const float*)d_in[5];
    const float* conv_b     = (const float*)d_in[6];
    const float* bn_gamma   = (const float*)d_in[7];
    const float* bn_beta    = (const float*)d_in[8];
    float* out = (float*)d_out;

    static int configured = 0;
    if (!configured) {
        cudaFuncSetAttribute(k1t_dft,  cudaFuncAttributeMaxDynamicSharedMemorySize, K1T_SMEM);
        cudaFuncSetAttribute(k4t_conv, cudaFuncAttributeMaxDynamicSharedMemorySize, K4T_SMEM);
        configured = 1;
    }

    k0_prep<<<69, 512>>>(conv_w);                // A-fp16 + twiddles (35072 items)
    k1t_dft<<<BCn*Ln, 256, K1T_SMEM>>>(x);       // 4096 blocks, tensor DFT
    k2_ldft<<<BCn*4, 448>>>(x);
    k3_calib<<<BLn, 64>>>(temporal_w, temporal_b, fc_w, fc_b, conv_b);
    k4t_conv<<<dim3(TILES, BLn), 448, K4T_SMEM>>>(x, conv_w);
    k4b_stats<<<Cn, 256>>>();
    k5_bnsilu<<<NTOT/1024, 256>>>(bn_gamma, bn_beta, out);
}

// round 16
// speedup vs baseline: 2.1045x; 1.3037x over previous
#include <cuda_runtime.h>
#include <cuda_fp16.h>
#include <math.h>
#include <stdint.h>

#define Bn 8
#define Ln 8
#define Cn 64
#define Hn 56
#define Wn 56
#define HWn 3136
#define BCn (Bn*Cn)        // 512
#define BLn (Bn*Ln)        // 64
#define NTOT (BLn*Cn*HWn)  // 12,845,056
#define KWC 29             // compact kw count (Hermitian half)
#define NPOS (56*KWC)      // 1624 positions per slab
#define TILES 28           // k4t: 2 output rows per tile
#define NBLK (BLn*TILES)   // 1792 BN-partial slots

__device__ __forceinline__ void mma_f16(float* d, const uint32_t* a, const uint32_t* b) {
    asm volatile(
        "mma.sync.aligned.m16n8k16.row.col.f32.f16.f16.f32 "
        "{%0,%1,%2,%3}, {%4,%5,%6,%7}, {%8,%9}, {%0,%1,%2,%3};\n"
        : "+f"(d[0]), "+f"(d[1]), "+f"(d[2]), "+f"(d[3])
        : "r"(a[0]), "r"(a[1]), "r"(a[2]), "r"(a[3]), "r"(b[0]), "r"(b[1]));
}

// ---------------- scratch (device globals; no runtime allocation) ----------
__device__ float  g_F2re[BCn*Ln*NPOS];  // compact 2D-DFT real plane (~26.6MB)
__device__ float  g_F2im[BCn*Ln*NPOS];  // compact 2D-DFT imag plane
__device__ __half g_yh[NTOT];           // pre-BN conv output, fp16 (~25.7MB)
__device__ float  g_ppart[BCn*4*Ln];    // pooled partials
__device__ float  g_s[BLn*Cn];          // per (b,l,ci) input-channel scale
__device__ float  g_fb[BLn*Cn];         // per (b,l,co) dynamic bias
__device__ __align__(16) uint32_t g_Ah[36*512];   // fp16 conv weights [chunk][co][8]
__device__ uint32_t g_WBh[32*64];       // fp16 stage-B twiddles [kpair][col]
__device__ uint32_t g_WCh[112*56];      // fp16 stage-C twiddles [row][kpair]
__device__ float  g_bnsum2[Cn*NBLK];
__device__ float  g_bnsq2[Cn*NBLK];
__device__ float  g_mean[Cn];
__device__ float  g_invstd[Cn];

// twiddle value helpers (host math replicated on device)
__device__ __forceinline__ float wb_val(int r, int cc) {
    if (r >= 56) return 0.f;
    int kw = cc & 31;
    float sv, cv;
    sincosf(-6.28318530717958647692f * (float)((r*kw) % 56) / 56.f, &sv, &cv);
    return (cc < 32) ? cv : sv;
}
__device__ __forceinline__ float wc_val(int r, int k) {
    int rr = (r < 56) ? r : r - 56;
    int kk = (k < 56) ? k : k - 56;
    float sv, cv;
    sincosf(-6.28318530717958647692f * (float)((rr*kk) % 56) / 56.f, &sv, &cv);
    if (r < 56) return (k < 56) ? cv : -sv;
    return (k < 56) ? sv : cv;
}

// ============================================================================
// K0: merged one-shot prep: conv-A fp16 fragments + fp16 twiddle pair tables.
// ============================================================================
__global__ __launch_bounds__(512) void k0_prep(const float* __restrict__ convw) {
    int e = blockIdx.x*512 + threadIdx.x;
    if (e < 18432) {
        int c  = e >> 9;
        int r9 = e & 511;
        int co = r9 >> 3;
        int p  = r9 & 7;
        int t  = p >> 1, j = p & 1;
        int ci  = (c & 3)*16 + 2*t + 8*j;
        int tap = c >> 2;
        float f0 = convw[(co*64 + ci    )*9 + tap];
        float f1 = convw[(co*64 + ci + 1)*9 + tap];
        __half2 h2 = __floats2half2_rn(f0, f1);
        g_Ah[e] = *(uint32_t*)&h2;
    } else if (e < 18432 + 2048) {
        int idx = e - 18432;
        int kp = idx >> 6, col = idx & 63;
        __half2 h2 = __floats2half2_rn(wb_val(2*kp, col), wb_val(2*kp + 1, col));
        g_WBh[idx] = *(uint32_t*)&h2;
    } else if (e < 18432 + 2048 + 6272) {
        int idx = e - 18432 - 2048;
        int row = idx / 56, kp = idx % 56;
        __half2 h2 = __floats2half2_rn(wc_val(row, 2*kp), wc_val(row, 2*kp + 1));
        g_WCh[idx] = *(uint32_t*)&h2;
    }
}

// ============================================================================
// K1T v3: fp16 tensor-core 2D DFT per slab (m16n8k16). Twiddles via LDG.
// Stage B: T1(64x64) = X(64x[56 pad 64]) @ WB  -> 128 MMAs
// Stage C: T2(112x32) = WC(112x112) @ T1stack  -> 196 MMAs
// smem: Xs 64x36 words + T1h 56x40 words = 18,176 B.
// Bank audit: A loads 4g+tg (distinct), T1 B loads 8tg+g (distinct).
// ============================================================================
#define K1T_SMEM ((2304 + 2240)*4)   // 18,176 B

__global__ __launch_bounds__(256, 4) void k1t_dft(const float* __restrict__ x) {
    extern __shared__ uint32_t sm1[];
    uint32_t* Xs  = sm1;            // [64 row][36 wordpair pitch]
    uint32_t* T1w = sm1 + 2304;     // [56 kpair][40 col pitch]
    __half*   T1h = (__half*)T1w;

    int slab = blockIdx.x;          // bc*8 + l
    int bc = slab >> 3, l = slab & 7;
    int b = bc >> 6, c = bc & 63;
    int tid = threadIdx.x;
    int wrp = tid >> 5, lane = tid & 31;
    int g = lane >> 2, tg = lane & 3;

    const float2* xp2 = (const float2*)(x + (size_t)((b*Ln + l)*Cn + c) * HWn);

    // stage X as fp16 pairs; rows>=56 and wordpairs>=28 are zero (K pad)
    for (int e = tid; e < 2048; e += 256) {
        int row = e >> 5, wp = e & 31;
        float2 v = make_float2(0.f, 0.f);
        if (row < 56 && wp < 28) v = xp2[row*28 + wp];
        __half2 h2 = __floats2half2_rn(v.x, v.y);
        Xs[row*36 + wp] = *(uint32_t*)&h2;
    }
    __syncthreads();

    // ---- Stage B: warp -> m-tile (wrp&3), n-tiles (wrp>>2)*4 .. +3
    {
        int mt = wrp & 3;
        int ng = (wrp >> 2) * 4;
        float accB[4][4];
        #pragma unroll
        for (int i = 0; i < 4; ++i)
            #pragma unroll
            for (int j = 0; j < 4; ++j) accB[i][j] = 0.f;

        #pragma unroll
        for (int kc = 0; kc < 4; ++kc) {
            int ab = (mt*16 + g)*36 + kc*8 + tg;
            uint32_t a[4];
            a[0] = Xs[ab];           a[1] = Xs[ab + 8*36];
            a[2] = Xs[ab + 4];       a[3] = Xs[ab + 8*36 + 4];
            int kb0 = (kc*8 + tg)*64;
            int kb1 = (kc*8 + tg + 4)*64;
            #pragma unroll
            for (int i = 0; i < 4; ++i) {
                int ncol = (ng + i)*8 + g;
                uint32_t bfr[2] = { __ldg(&g_WBh[kb0 + ncol]), __ldg(&g_WBh[kb1 + ncol]) };
                mma_f16(accB[i], a, bfr);
            }
        }
        // store T1 as stacked-k half pairs: row tr (h or 56+h), col kw&31
        #pragma unroll
        for (int i = 0; i < 4; ++i)
            #pragma unroll
            for (int j = 0; j < 4; ++j) {
                int h   = mt*16 + g + (j >> 1)*8;
                int col = (ng + i)*8 + tg*2 + (j & 1);
                if (h < 56) {
                    int tr = (col < 32) ? h : 56 + h;
                    int tc = col & 31;
                    T1h[((tr >> 1)*40 + tc)*2 + (tr & 1)] = __float2half_rn(accB[i][j]);
                }
            }
    }
    __syncthreads();

    // ---- Stage C: 14 units (7 m-tiles x 2 n-halves); warp strided
    float* re = g_F2re + (size_t)slab * NPOS;
    float* im = g_F2im + (size_t)slab * NPOS;
    for (int u = wrp; u < 14; u += 8) {
        int mt = u >> 1, nh = u & 1;
        float accC[2][4];
        #pragma unroll
        for (int i = 0; i < 2; ++i)
            #pragma unroll
            for (int j = 0; j < 4; ++j) accC[i][j] = 0.f;

        #pragma unroll
        for (int kc = 0; kc < 7; ++kc) {
            int ar = (mt*16 + g)*56 + kc*8 + tg;
            uint32_t a[4];
            a[0] = __ldg(&g_WCh[ar]);           a[1] = __ldg(&g_WCh[ar + 8*56]);
            a[2] = __ldg(&g_WCh[ar + 4]);       a[3] = __ldg(&g_WCh[ar + 8*56 + 4]);
            #pragma unroll
            for (int i = 0; i < 2; ++i) {
                int ncol = (nh*2 + i)*8 + g;
                uint32_t bfr[2] = { T1w[(kc*8 + tg)*40 + ncol],
                                    T1w[(kc*8 + tg + 4)*40 + ncol] };
                mma_f16(accC[i], a, bfr);
            }
        }
        #pragma unroll
        for (int i = 0; i < 2; ++i) {
            int nt = nh*2 + i;
            #pragma unroll
            for (int j = 0; j < 4; ++j) {
                int r  = mt*16 + g + (j >> 1)*8;
                int kw = nt*8 + tg*2 + (j & 1);
                if (kw <= 28) {
                    if (r < 56) re[r*KWC + kw] = accC[i][j];
                    else        im[(r - 56)*KWC + kw] = accC[i][j];
                }
            }
        }
    }
}

// ============================================================================
// K2: 8-point DFT along L + magnitude; mirror reuse. (unchanged)
// ============================================================================
__global__ __launch_bounds__(448) void k2_ldft(const float* __restrict__ x) {
    int bx = blockIdx.x;
    int bc = bx >> 2, jb = bx & 3;
    int b  = bc >> 6, c = bc & 63;
    int tid = threadIdx.x;
    int idx = jb * 448 + tid;

    float contrib[8];
    #pragma unroll
    for (int k = 0; k < 8; ++k) contrib[k] = 0.f;

    if (idx < NPOS) {
        int kh = idx / KWC, kw = idx % KWC;
        int p  = kh*56 + kw;
        int pm = ((56 - kh) % 56)*56 + ((56 - kw) % 56);
        bool do_m = (kw >= 1 && kw <= 27);

        const float* f2r = g_F2re + (size_t)(bc*Ln) * NPOS + idx;
        const float* f2i = g_F2im + (size_t)(bc*Ln) * NPOS + idx;
        float fr[8], fi[8];
        #pragma unroll
        for (int l2 = 0; l2 < 8; ++l2) {
            fr[l2] = f2r[(size_t)l2 * NPOS];
            fi[l2] = f2i[(size_t)l2 * NPOS];
        }

        const float RT = 0.70710678118654752f;
        const float twc[8] = {1.f,  RT, 0.f, -RT, -1.f, -RT, 0.f,  RT};
        const float tws[8] = {0.f, -RT, -1.f, -RT, 0.f,  RT, 1.f,  RT};
        const float SCALE = 0.01f / 158.39507568359375f;

        float mag[8];
        #pragma unroll
        for (int k = 0; k < 8; ++k) {
            float re = 0.f, im = 0.f;
            #pragma unroll
            for (int l2 = 0; l2 < 8; ++l2) {
                int j = (l2 * k) & 7;
                re += twc[j]*fr[l2] - tws[j]*fi[l2];
                im += twc[j]*fi[l2] + tws[j]*fr[l2];
            }
            mag[k] = sqrtf(re*re + im*im);
        }

        #pragma unroll
        for (int k = 0; k < 8; ++k) {
            const float* xl = x + (size_t)((b*Ln + k)*Cn + c) * HWn;
            float v = xl[p] * (1.0f + SCALE * mag[k]);
            if (do_m)
                v += xl[pm] * (1.0f + SCALE * mag[(8 - k) & 7]);
            contrib[k] = v;
        }
    }

    #pragma unroll
    for (int k = 0; k < 8; ++k)
        #pragma unroll
        for (int off = 16; off > 0; off >>= 1)
            contrib[k] += __shfl_down_sync(0xffffffff, contrib[k], off);

    __shared__ float ws[14][8];
    int wid = tid >> 5, lane = tid & 31;
    if (lane == 0) {
        #pragma unroll
        for (int k = 0; k < 8; ++k) ws[wid][k] = contrib[k];
    }
    __syncthreads();
    if (tid < 8) {
        float s = 0.f;
        #pragma unroll
        for (int w2 = 0; w2 < 14; ++w2) s += ws[w2][tid];
        g_ppart[(bc*4 + jb)*8 + tid] = s;
    }
}

// ============================================================================
// K3: pooled -> calibration. (unchanged)
// ============================================================================
__global__ __launch_bounds__(64) void k3_calib(
    const float* __restrict__ tw_, const float* __restrict__ tb,
    const float* __restrict__ fcw, const float* __restrict__ fcb,
    const float* __restrict__ convb)
{
    int bl = blockIdx.x;
    int b  = bl >> 3, l = bl & 7;
    int tid = threadIdx.x;

    __shared__ float pooled[64];
    __shared__ float fcp[65];

    float s = 0.f;
    #pragma unroll
    for (int j = 0; j < 4; ++j)
        s += g_ppart[((b*Cn + tid)*4 + j)*8 + l];
    float pv = s * (1.0f / 3136.0f);
    pooled[tid] = pv;
    fcp[tid] = fcw[tid] * pv;
    __syncthreads();

    float calib = tb[tid];
    #pragma unroll 8
    for (int c = 0; c < 64; ++c) calib += tw_[tid*64 + c] * pooled[c];
    g_s[bl*Cn + tid] = calib + 1.0f;

    if (tid == 0) {
        float f = fcb[0];
        for (int c = 0; c < 64; ++c) f += fcp[c];
        fcp[64] = f + 1.0f;
    }
    __syncthreads();
    g_fb[bl*Cn + tid] = convb[tid] * fcp[64];
}

// ============================================================================
// K4T: fp16 implicit-GEMM conv via mma.m16n8k16. (unchanged from R15 winner)
// ============================================================================
#define K4T_SMEM (16704*2)   // 33,408 B

__global__ __launch_bounds__(448, 2) void k4t_conv(const float* __restrict__ x,
                                                   const float* __restrict__ convw) {
    extern __shared__ uint32_t xs32[];      // 8352 u32 = [4][58][36 words]
    __shared__ float ssh[64];
    __shared__ float red_s[14][32];
    __shared__ float red_q[14][32];

    int tile = blockIdx.x;   // 0..27
    int bl   = blockIdx.y;   // 0..63
    int tid  = threadIdx.x;
    int w    = tid >> 5;
    int lane = tid & 31;
    int g    = lane >> 2;    // 0..7
    int tg   = lane & 3;     // 0..3
    int mw   = w & 1;
    int nw   = w >> 1;       // 0..6
    int mwbase = mw * 32;

    if (tid < 64) ssh[tid] = g_s[bl*64 + tid];
    __syncthreads();

    const float* xb = x + (size_t)bl * 64 * HWn;

    for (int wi = w; wi < 256; wi += 14) {
        int cb  = wi & 7;
        int r   = (wi >> 3) & 3;
        int cip = wi >> 5;              // 0..7
        int c   = cb*8 + (lane & 7);    // 0..63 (valid < 58)
        int p   = cip*4 + (lane >> 3);  // ci-pair 0..31
        if (c < 58) {
            int gr = 2*tile - 1 + r;
            int gc = c - 1;
            float v0 = 0.f, v1 = 0.f;
            if (gr >= 0 && gr < 56 && gc >= 0 && gc < 56) {
                int ci = p*2;
                int off = gr*56 + gc;
                v0 = xb[(size_t)ci*HWn + off] * ssh[ci];
                v1 = xb[(size_t)(ci+1)*HWn + off] * ssh[ci+1];
            }
            __half2 h2 = __floats2half2_rn(v0, v1);
            xs32[(r*58 + c)*36 + p] = *(uint32_t*)&h2;
        }
    }
    __syncthreads();

    int colb[2], rsv[2];
    #pragma unroll
    for (int nf = 0; nf < 2; ++nf) {
        int px = nw*16 + nf*8 + g;
        int rs = (px >= 56) ? 1 : 0;
        rsv[nf]  = rs;
        colb[nf] = px - rs*56;
    }

    float acc[2][2][4];
    #pragma unroll
    for (int mf = 0; mf < 2; ++mf)
        #pragma unroll
        for (int nf = 0; nf < 2; ++nf)
            #pragma unroll
            for (int j = 0; j < 4; ++j) acc[mf][nf][j] = 0.f;

    int aoff0 = (mwbase + g)*8 + 2*tg;
    #pragma unroll
    for (int dr = 0; dr < 3; ++dr) {
        #pragma unroll
        for (int dc2 = 0; dc2 < 3; ++dc2) {
            int tap = dr*3 + dc2;
            #pragma unroll
            for (int q = 0; q < 4; ++q) {
                const uint32_t* ab = g_Ah + (tap*4 + q)*512;
                uint32_t a[2][4];
                #pragma unroll
                for (int mf = 0; mf < 2; ++mf) {
                    uint2 p0 = __ldg((const uint2*)(ab + aoff0 + mf*128));
                    uint2 p1 = __ldg((const uint2*)(ab + aoff0 + mf*128 + 64));
                    a[mf][0] = p0.x; a[mf][1] = p1.x; a[mf][2] = p0.y; a[mf][3] = p1.y;
                }
                uint32_t b[2][2];
                #pragma unroll
                for (int nf = 0; nf < 2; ++nf) {
                    int widx = ((rsv[nf] + dr)*58 + colb[nf] + dc2)*36 + q*8 + tg;
                    b[nf][0] = xs32[widx];
                    b[nf][1] = xs32[widx + 4];
                }
                #pragma unroll
                for (int mf = 0; mf < 2; ++mf)
                    #pragma unroll
                    for (int nf = 0; nf < 2; ++nf)
                        mma_f16(acc[mf][nf], a[mf], b[nf]);
            }
        }
    }

    float psum[2][2] = {{0.f,0.f},{0.f,0.f}};
    float psq [2][2] = {{0.f,0.f},{0.f,0.f}};
    #pragma unroll
    for (int mf = 0; mf < 2; ++mf) {
        #pragma unroll
        for (int nf = 0; nf < 2; ++nf) {
            #pragma unroll
            for (int hi = 0; hi < 2; ++hi) {
                int co = mwbase + mf*16 + g + hi*8;
                float fbv = g_fb[bl*64 + co];
                int px0 = nw*16 + nf*8 + tg*2;
                int rs = (px0 >= 56) ? 1 : 0;
                int row = 2*tile + rs;
                int col = px0 - rs*56;
                int loc = co*HWn + row*56 + col;
                float v0 = acc[mf][nf][hi*2 + 0] + fbv + xb[loc];
                float v1 = acc[mf][nf][hi*2 + 1] + fbv + xb[loc + 1];
                __half2 h2 = __floats2half2_rn(v0, v1);
                *(__half2*)(g_yh + (size_t)bl*64*HWn + loc) = h2;
                float r0 = __half2float(__low2half(h2));
                float r1 = __half2float(__high2half(h2));
                psum[mf][hi] += r0 + r1;
                psq [mf][hi] += r0*r0 + r1*r1;
            }
        }
    }
    #pragma unroll
    for (int mf = 0; mf < 2; ++mf)
        #pragma unroll
        for (int hi = 0; hi < 2; ++hi) {
            float s = psum[mf][hi], q = psq[mf][hi];
            s += __shfl_down_sync(0xffffffffu, s, 2, 4);
            s += __shfl_down_sync(0xffffffffu, s, 1, 4);
            q += __shfl_down_sync(0xffffffffu, q, 2, 4);
            q += __shfl_down_sync(0xffffffffu, q, 1, 4);
            if (tg == 0) {
                red_s[w][mf*16 + hi*8 + g] = s;
                red_q[w][mf*16 + hi*8 + g] = q;
            }
        }
    __syncthreads();
    if (tid < 64) {
        int co = tid;
        int mw2 = co >> 5; int rem = co & 31;
        int mf = rem >> 4; int g8 = rem & 15;
        int hi = g8 >> 3;  int g2 = g8 & 7;
        int idx = mf*16 + hi*8 + g2;
        float s = 0.f, q = 0.f;
        #pragma unroll
        for (int nw2 = 0; nw2 < 7; ++nw2) {
            s += red_s[nw2*2 + mw2][idx];
            q += red_q[nw2*2 + mw2][idx];
        }
        g_bnsum2[co*NBLK + bl*TILES + tile] = s;
        g_bnsq2 [co*NBLK + bl*TILES + tile] = q;
    }
}

// ============================================================================
// K4b: final BN statistics. (unchanged)
// ============================================================================
__global__ __launch_bounds__(256) void k4b_stats() {
    int co  = blockIdx.x;
    int tid = threadIdx.x;
    float s = 0.f, q = 0.f;
    for (int i = tid; i < NBLK; i += 256) {
        s += g_bnsum2[co*NBLK + i];
        q += g_bnsq2 [co*NBLK + i];
    }
    #pragma unroll
    for (int off = 16; off > 0; off >>= 1) {
        s += __shfl_down_sync(0xffffffffu, s, off);
        q += __shfl_down_sync(0xffffffffu, q, off);
    }
    __shared__ float ws2[8], wq2[8];
    int wid = tid >> 5, lane = tid & 31;
    if (lane == 0) { ws2[wid] = s; wq2[wid] = q; }
    __syncthreads();
    if (tid == 0) {
        float S = 0.f, Q = 0.f;
        #pragma unroll
        for (int i = 0; i < 8; ++i) { S += ws2[i]; Q += wq2[i]; }
        const float invN = 1.0f / (float)(BLn * HWn);
        float mean = S * invN;
        float var  = Q * invN - mean*mean;
        g_mean[co]   = mean;
        g_invstd[co] = rsqrtf(var + 1e-5f);
    }
}

// ============================================================================
// K5: BN normalize + affine + SiLU -> d_out; reads fp16 y. (unchanged)
// ============================================================================
__global__ __launch_bounds__(256) void k5_bnsilu(const float* __restrict__ gamma,
                                                 const float* __restrict__ beta,
                                                 float* __restrict__ out) {
    int i4 = blockIdx.x * 256 + threadIdx.x;
    int c = ((i4 * 4) / HWn) & 63;
    uint2 yv = ((const uint2*)g_yh)[i4];
    __half2 h01 = *(__half2*)&yv.x;
    __half2 h23 = *(__half2*)&yv.y;
    float2 f01 = __half22float2(h01);
    float2 f23 = __half22float2(h23);
    float m = g_mean[c], is = g_invstd[c] * gamma[c], bt = beta[c];
    float4 o;
    o.x = (f01.x - m) * is + bt;
    o.y = (f01.y - m) * is + bt;
    o.z = (f23.x - m) * is + bt;
    o.w = (f23.y - m) * is + bt;
    o.x = o.x / (1.0f + __expf(-o.x));
    o.y = o.y / (1.0f + __expf(-o.y));
    o.z = o.z / (1.0f + __expf(-o.z));
    o.w = o.w / (1.0f + __expf(-o.w));
    ((float4*)out)[i4] = o;
}

// ============================================================================
extern "C" void kernel_launch(void* const* d_in, const int* in_sizes, int n_in,
                              void* d_out, int out_size) {
    const float* x          = (const float*)d_in[0];
    const float* temporal_w = (const float*)d_in[1];
    const float* temporal_b = (const float*)d_in[2];
    const float* fc_w       = (const float*)d_in[3];
    const float* fc_b       = (const float*)d_in[4];
    const float* conv_w     = (const float*)d_in[5];
    const float* conv_b     = (const float*)d_in[6];
    const float* bn_gamma   = (const float*)d_in[7];
    const float* bn_beta    = (const float*)d_in[8];
    float* out = (float*)d_out;

    static int configured = 0;
    if (!configured) {
        cudaFuncSetAttribute(k1t_dft,  cudaFuncAttributeMaxDynamicSharedMemorySize, K1T_SMEM);
        cudaFuncSetAttribute(k4t_conv, cudaFuncAttributeMaxDynamicSharedMemorySize, K4T_SMEM);
        configured = 1;
    }

    k0_prep<<<53, 512>>>(conv_w);                // Ah + WBh + WCh (26752 items)
    k1t_dft<<<BCn*Ln, 256, K1T_SMEM>>>(x);       // 4096 blocks, fp16 tensor DFT
    k2_ldft<<<BCn*4, 448>>>(x);
    k3_calib<<<BLn, 64>>>(temporal_w, temporal_b, fc_w, fc_b, conv_b);
    k4t_conv<<<dim3(TILES, BLn), 448, K4T_SMEM>>>(x, conv_w);
    k4b_stats<<<Cn, 256>>>();
    k5_bnsilu<<<NTOT/1024, 256>>>(bn_gamma, bn_beta, out);
}

// round 17
// speedup vs baseline: 2.2192x; 1.0545x over previous
#include <cuda_runtime.h>
#include <cuda_fp16.h>
#include <math.h>
#include <stdint.h>

#define Bn 8
#define Ln 8
#define Cn 64
#define Hn 56
#define Wn 56
#define HWn 3136
#define BCn (Bn*Cn)        // 512
#define BLn (Bn*Ln)        // 64
#define NTOT (BLn*Cn*HWn)  // 12,845,056
#define KWC 29             // compact kw count (Hermitian half)
#define NPOS (56*KWC)      // 1624 positions per slab
#define TILES 28           // k4t: 2 output rows per tile
#define NBLK (BLn*TILES)   // 1792 BN-partial slots

__device__ __forceinline__ void mma_f16(float* d, const uint32_t* a, const uint32_t* b) {
    asm volatile(
        "mma.sync.aligned.m16n8k16.row.col.f32.f16.f16.f32 "
        "{%0,%1,%2,%3}, {%4,%5,%6,%7}, {%8,%9}, {%0,%1,%2,%3};\n"
        : "+f"(d[0]), "+f"(d[1]), "+f"(d[2]), "+f"(d[3])
        : "r"(a[0]), "r"(a[1]), "r"(a[2]), "r"(a[3]), "r"(b[0]), "r"(b[1]));
}

// ---------------- scratch (device globals; no runtime allocation) ----------
__device__ __half g_F2re[BCn*Ln*NPOS]; // compact 2D-DFT real plane, fp16 (~13.3MB)
__device__ __half g_F2im[BCn*Ln*NPOS]; // compact 2D-DFT imag plane, fp16
__device__ __half g_yh[NTOT];          // pre-BN conv output, fp16 (~25.7MB)
__device__ float  g_ppart[BCn*4*Ln];   // pooled partials
__device__ float  g_s[BLn*Cn];         // per (b,l,ci) input-channel scale
__device__ float  g_fb[BLn*Cn];        // per (b,l,co) dynamic bias
__device__ __align__(16) uint32_t g_Ah[36*512];   // fp16 conv weights [chunk][co][8]
__device__ uint32_t g_WBh[32*64];      // fp16 stage-B twiddles [kpair][col]
__device__ uint32_t g_WCh[112*56];     // fp16 stage-C twiddles [row][kpair]
__device__ float  g_bnsum2[Cn*NBLK];
__device__ float  g_bnsq2[Cn*NBLK];
__device__ float  g_mean[Cn];
__device__ float  g_invstd[Cn];

// twiddle value helpers
__device__ __forceinline__ float wb_val(int r, int cc) {
    if (r >= 56) return 0.f;
    int kw = cc & 31;
    float sv, cv;
    sincosf(-6.28318530717958647692f * (float)((r*kw) % 56) / 56.f, &sv, &cv);
    return (cc < 32) ? cv : sv;
}
__device__ __forceinline__ float wc_val(int r, int k) {
    int rr = (r < 56) ? r : r - 56;
    int kk = (k < 56) ? k : k - 56;
    float sv, cv;
    sincosf(-6.28318530717958647692f * (float)((rr*kk) % 56) / 56.f, &sv, &cv);
    if (r < 56) return (k < 56) ? cv : -sv;
    return (k < 56) ? sv : cv;
}

// ============================================================================
// K0: merged one-shot prep: conv-A fp16 fragments + fp16 twiddle pair tables.
// ============================================================================
__global__ __launch_bounds__(512) void k0_prep(const float* __restrict__ convw) {
    int e = blockIdx.x*512 + threadIdx.x;
    if (e < 18432) {
        int c  = e >> 9;
        int r9 = e & 511;
        int co = r9 >> 3;
        int p  = r9 & 7;
        int t  = p >> 1, j = p & 1;
        int ci  = (c & 3)*16 + 2*t + 8*j;
        int tap = c >> 2;
        float f0 = convw[(co*64 + ci    )*9 + tap];
        float f1 = convw[(co*64 + ci + 1)*9 + tap];
        __half2 h2 = __floats2half2_rn(f0, f1);
        g_Ah[e] = *(uint32_t*)&h2;
    } else if (e < 18432 + 2048) {
        int idx = e - 18432;
        int kp = idx >> 6, col = idx & 63;
        __half2 h2 = __floats2half2_rn(wb_val(2*kp, col), wb_val(2*kp + 1, col));
        g_WBh[idx] = *(uint32_t*)&h2;
    } else if (e < 18432 + 2048 + 6272) {
        int idx = e - 18432 - 2048;
        int row = idx / 56, kp = idx % 56;
        __half2 h2 = __floats2half2_rn(wc_val(row, 2*kp), wc_val(row, 2*kp + 1));
        g_WCh[idx] = *(uint32_t*)&h2;
    }
}

// ============================================================================
// K1T: fp16 tensor-core 2D DFT per slab (m16n8k16); twiddles via LDG;
// F2 outputs now stored as fp16. (otherwise unchanged from R16 winner)
// ============================================================================
#define K1T_SMEM ((2304 + 2240)*4)   // 18,176 B

__global__ __launch_bounds__(256, 4) void k1t_dft(const float* __restrict__ x) {
    extern __shared__ uint32_t sm1[];
    uint32_t* Xs  = sm1;            // [64 row][36 wordpair pitch]
    uint32_t* T1w = sm1 + 2304;     // [56 kpair][40 col pitch]
    __half*   T1h = (__half*)T1w;

    int slab = blockIdx.x;          // bc*8 + l
    int bc = slab >> 3, l = slab & 7;
    int b = bc >> 6, c = bc & 63;
    int tid = threadIdx.x;
    int wrp = tid >> 5, lane = tid & 31;
    int g = lane >> 2, tg = lane & 3;

    const float2* xp2 = (const float2*)(x + (size_t)((b*Ln + l)*Cn + c) * HWn);

    for (int e = tid; e < 2048; e += 256) {
        int row = e >> 5, wp = e & 31;
        float2 v = make_float2(0.f, 0.f);
        if (row < 56 && wp < 28) v = xp2[row*28 + wp];
        __half2 h2 = __floats2half2_rn(v.x, v.y);
        Xs[row*36 + wp] = *(uint32_t*)&h2;
    }
    __syncthreads();

    // ---- Stage B
    {
        int mt = wrp & 3;
        int ng = (wrp >> 2) * 4;
        float accB[4][4];
        #pragma unroll
        for (int i = 0; i < 4; ++i)
            #pragma unroll
            for (int j = 0; j < 4; ++j) accB[i][j] = 0.f;

        #pragma unroll
        for (int kc = 0; kc < 4; ++kc) {
            int ab = (mt*16 + g)*36 + kc*8 + tg;
            uint32_t a[4];
            a[0] = Xs[ab];           a[1] = Xs[ab + 8*36];
            a[2] = Xs[ab + 4];       a[3] = Xs[ab + 8*36 + 4];
            int kb0 = (kc*8 + tg)*64;
            int kb1 = (kc*8 + tg + 4)*64;
            #pragma unroll
            for (int i = 0; i < 4; ++i) {
                int ncol = (ng + i)*8 + g;
                uint32_t bfr[2] = { __ldg(&g_WBh[kb0 + ncol]), __ldg(&g_WBh[kb1 + ncol]) };
                mma_f16(accB[i], a, bfr);
            }
        }
        #pragma unroll
        for (int i = 0; i < 4; ++i)
            #pragma unroll
            for (int j = 0; j < 4; ++j) {
                int h   = mt*16 + g + (j >> 1)*8;
                int col = (ng + i)*8 + tg*2 + (j & 1);
                if (h < 56) {
                    int tr = (col < 32) ? h : 56 + h;
                    int tc = col & 31;
                    T1h[((tr >> 1)*40 + tc)*2 + (tr & 1)] = __float2half_rn(accB[i][j]);
                }
            }
    }
    __syncthreads();

    // ---- Stage C
    __half* re = g_F2re + (size_t)slab * NPOS;
    __half* im = g_F2im + (size_t)slab * NPOS;
    for (int u = wrp; u < 14; u += 8) {
        int mt = u >> 1, nh = u & 1;
        float accC[2][4];
        #pragma unroll
        for (int i = 0; i < 2; ++i)
            #pragma unroll
            for (int j = 0; j < 4; ++j) accC[i][j] = 0.f;

        #pragma unroll
        for (int kc = 0; kc < 7; ++kc) {
            int ar = (mt*16 + g)*56 + kc*8 + tg;
            uint32_t a[4];
            a[0] = __ldg(&g_WCh[ar]);           a[1] = __ldg(&g_WCh[ar + 8*56]);
            a[2] = __ldg(&g_WCh[ar + 4]);       a[3] = __ldg(&g_WCh[ar + 8*56 + 4]);
            #pragma unroll
            for (int i = 0; i < 2; ++i) {
                int ncol = (nh*2 + i)*8 + g;
                uint32_t bfr[2] = { T1w[(kc*8 + tg)*40 + ncol],
                                    T1w[(kc*8 + tg + 4)*40 + ncol] };
                mma_f16(accC[i], a, bfr);
            }
        }
        #pragma unroll
        for (int i = 0; i < 2; ++i) {
            int nt = nh*2 + i;
            #pragma unroll
            for (int j = 0; j < 4; ++j) {
                int r  = mt*16 + g + (j >> 1)*8;
                int kw = nt*8 + tg*2 + (j & 1);
                if (kw <= 28) {
                    __half hv = __float2half_rn(accC[i][j]);
                    if (r < 56) re[r*KWC + kw] = hv;
                    else        im[(r - 56)*KWC + kw] = hv;
                }
            }
        }
    }
}

// ============================================================================
// K2: 8-point DFT along L + magnitude; mirror reuse. F2 reads now fp16.
// ============================================================================
__global__ __launch_bounds__(448) void k2_ldft(const float* __restrict__ x) {
    int bx = blockIdx.x;
    int bc = bx >> 2, jb = bx & 3;
    int b  = bc >> 6, c = bc & 63;
    int tid = threadIdx.x;
    int idx = jb * 448 + tid;

    float contrib[8];
    #pragma unroll
    for (int k = 0; k < 8; ++k) contrib[k] = 0.f;

    if (idx < NPOS) {
        int kh = idx / KWC, kw = idx % KWC;
        int p  = kh*56 + kw;
        int pm = ((56 - kh) % 56)*56 + ((56 - kw) % 56);
        bool do_m = (kw >= 1 && kw <= 27);

        const __half* f2r = g_F2re + (size_t)(bc*Ln) * NPOS + idx;
        const __half* f2i = g_F2im + (size_t)(bc*Ln) * NPOS + idx;
        float fr[8], fi[8];
        #pragma unroll
        for (int l2 = 0; l2 < 8; ++l2) {
            fr[l2] = __half2float(__ldg(f2r + (size_t)l2 * NPOS));
            fi[l2] = __half2float(__ldg(f2i + (size_t)l2 * NPOS));
        }

        const float RT = 0.70710678118654752f;
        const float twc[8] = {1.f,  RT, 0.f, -RT, -1.f, -RT, 0.f,  RT};
        const float tws[8] = {0.f, -RT, -1.f, -RT, 0.f,  RT, 1.f,  RT};
        const float SCALE = 0.01f / 158.39507568359375f;

        float mag[8];
        #pragma unroll
        for (int k = 0; k < 8; ++k) {
            float re = 0.f, im = 0.f;
            #pragma unroll
            for (int l2 = 0; l2 < 8; ++l2) {
                int j = (l2 * k) & 7;
                re += twc[j]*fr[l2] - tws[j]*fi[l2];
                im += twc[j]*fi[l2] + tws[j]*fr[l2];
            }
            mag[k] = sqrtf(re*re + im*im);
        }

        #pragma unroll
        for (int k = 0; k < 8; ++k) {
            const float* xl = x + (size_t)((b*Ln + k)*Cn + c) * HWn;
            float v = xl[p] * (1.0f + SCALE * mag[k]);
            if (do_m)
                v += xl[pm] * (1.0f + SCALE * mag[(8 - k) & 7]);
            contrib[k] = v;
        }
    }

    #pragma unroll
    for (int k = 0; k < 8; ++k)
        #pragma unroll
        for (int off = 16; off > 0; off >>= 1)
            contrib[k] += __shfl_down_sync(0xffffffff, contrib[k], off);

    __shared__ float ws[14][8];
    int wid = tid >> 5, lane = tid & 31;
    if (lane == 0) {
        #pragma unroll
        for (int k = 0; k < 8; ++k) ws[wid][k] = contrib[k];
    }
    __syncthreads();
    if (tid < 8) {
        float s = 0.f;
        #pragma unroll
        for (int w2 = 0; w2 < 14; ++w2) s += ws[w2][tid];
        g_ppart[(bc*4 + jb)*8 + tid] = s;
    }
}

// ============================================================================
// K3: pooled -> calibration. (unchanged)
// ============================================================================
__global__ __launch_bounds__(64) void k3_calib(
    const float* __restrict__ tw_, const float* __restrict__ tb,
    const float* __restrict__ fcw, const float* __restrict__ fcb,
    const float* __restrict__ convb)
{
    int bl = blockIdx.x;
    int b  = bl >> 3, l = bl & 7;
    int tid = threadIdx.x;

    __shared__ float pooled[64];
    __shared__ float fcp[65];

    float s = 0.f;
    #pragma unroll
    for (int j = 0; j < 4; ++j)
        s += g_ppart[((b*Cn + tid)*4 + j)*8 + l];
    float pv = s * (1.0f / 3136.0f);
    pooled[tid] = pv;
    fcp[tid] = fcw[tid] * pv;
    __syncthreads();

    float calib = tb[tid];
    #pragma unroll 8
    for (int c = 0; c < 64; ++c) calib += tw_[tid*64 + c] * pooled[c];
    g_s[bl*Cn + tid] = calib + 1.0f;

    if (tid == 0) {
        float f = fcb[0];
        for (int c = 0; c < 64; ++c) f += fcp[c];
        fcp[64] = f + 1.0f;
    }
    __syncthreads();
    g_fb[bl*Cn + tid] = convb[tid] * fcp[64];
}

// ============================================================================
// K4T: fp16 implicit-GEMM conv via mma.m16n8k16. (unchanged from R15 winner)
// ============================================================================
#define K4T_SMEM (16704*2)   // 33,408 B

__global__ __launch_bounds__(448, 2) void k4t_conv(const float* __restrict__ x,
                                                   const float* __restrict__ convw) {
    extern __shared__ uint32_t xs32[];      // 8352 u32 = [4][58][36 words]
    __shared__ float ssh[64];
    __shared__ float red_s[14][32];
    __shared__ float red_q[14][32];

    int tile = blockIdx.x;   // 0..27
    int bl   = blockIdx.y;   // 0..63
    int tid  = threadIdx.x;
    int w    = tid >> 5;
    int lane = tid & 31;
    int g    = lane >> 2;    // 0..7
    int tg   = lane & 3;     // 0..3
    int mw   = w & 1;
    int nw   = w >> 1;       // 0..6
    int mwbase = mw * 32;

    if (tid < 64) ssh[tid] = g_s[bl*64 + tid];
    __syncthreads();

    const float* xb = x + (size_t)bl * 64 * HWn;

    for (int wi = w; wi < 256; wi += 14) {
        int cb  = wi & 7;
        int r   = (wi >> 3) & 3;
        int cip = wi >> 5;              // 0..7
        int c   = cb*8 + (lane & 7);    // 0..63 (valid < 58)
        int p   = cip*4 + (lane >> 3);  // ci-pair 0..31
        if (c < 58) {
            int gr = 2*tile - 1 + r;
            int gc = c - 1;
            float v0 = 0.f, v1 = 0.f;
            if (gr >= 0 && gr < 56 && gc >= 0 && gc < 56) {
                int ci = p*2;
                int off = gr*56 + gc;
                v0 = xb[(size_t)ci*HWn + off] * ssh[ci];
                v1 = xb[(size_t)(ci+1)*HWn + off] * ssh[ci+1];
            }
            __half2 h2 = __floats2half2_rn(v0, v1);
            xs32[(r*58 + c)*36 + p] = *(uint32_t*)&h2;
        }
    }
    __syncthreads();

    int colb[2], rsv[2];
    #pragma unroll
    for (int nf = 0; nf < 2; ++nf) {
        int px = nw*16 + nf*8 + g;
        int rs = (px >= 56) ? 1 : 0;
        rsv[nf]  = rs;
        colb[nf] = px - rs*56;
    }

    float acc[2][2][4];
    #pragma unroll
    for (int mf = 0; mf < 2; ++mf)
        #pragma unroll
        for (int nf = 0; nf < 2; ++nf)
            #pragma unroll
            for (int j = 0; j < 4; ++j) acc[mf][nf][j] = 0.f;

    int aoff0 = (mwbase + g)*8 + 2*tg;
    #pragma unroll
    for (int dr = 0; dr < 3; ++dr) {
        #pragma unroll
        for (int dc2 = 0; dc2 < 3; ++dc2) {
            int tap = dr*3 + dc2;
            #pragma unroll
            for (int q = 0; q < 4; ++q) {
                const uint32_t* ab = g_Ah + (tap*4 + q)*512;
                uint32_t a[2][4];
                #pragma unroll
                for (int mf = 0; mf < 2; ++mf) {
                    uint2 p0 = __ldg((const uint2*)(ab + aoff0 + mf*128));
                    uint2 p1 = __ldg((const uint2*)(ab + aoff0 + mf*128 + 64));
                    a[mf][0] = p0.x; a[mf][1] = p1.x; a[mf][2] = p0.y; a[mf][3] = p1.y;
                }
                uint32_t b[2][2];
                #pragma unroll
                for (int nf = 0; nf < 2; ++nf) {
                    int widx = ((rsv[nf] + dr)*58 + colb[nf] + dc2)*36 + q*8 + tg;
                    b[nf][0] = xs32[widx];
                    b[nf][1] = xs32[widx + 4];
                }
                #pragma unroll
                for (int mf = 0; mf < 2; ++mf)
                    #pragma unroll
                    for (int nf = 0; nf < 2; ++nf)
                        mma_f16(acc[mf][nf], a[mf], b[nf]);
            }
        }
    }

    float psum[2][2] = {{0.f,0.f},{0.f,0.f}};
    float psq [2][2] = {{0.f,0.f},{0.f,0.f}};
    #pragma unroll
    for (int mf = 0; mf < 2; ++mf) {
        #pragma unroll
        for (int nf = 0; nf < 2; ++nf) {
            #pragma unroll
            for (int hi = 0; hi < 2; ++hi) {
                int co = mwbase + mf*16 + g + hi*8;
                float fbv = g_fb[bl*64 + co];
                int px0 = nw*16 + nf*8 + tg*2;
                int rs = (px0 >= 56) ? 1 : 0;
                int row = 2*tile + rs;
                int col = px0 - rs*56;
                int loc = co*HWn + row*56 + col;
                float v0 = acc[mf][nf][hi*2 + 0] + fbv + xb[loc];
                float v1 = acc[mf][nf][hi*2 + 1] + fbv + xb[loc + 1];
                __half2 h2 = __floats2half2_rn(v0, v1);
                *(__half2*)(g_yh + (size_t)bl*64*HWn + loc) = h2;
                float r0 = __half2float(__low2half(h2));
                float r1 = __half2float(__high2half(h2));
                psum[mf][hi] += r0 + r1;
                psq [mf][hi] += r0*r0 + r1*r1;
            }
        }
    }
    #pragma unroll
    for (int mf = 0; mf < 2; ++mf)
        #pragma unroll
        for (int hi = 0; hi < 2; ++hi) {
            float s = psum[mf][hi], q = psq[mf][hi];
            s += __shfl_down_sync(0xffffffffu, s, 2, 4);
            s += __shfl_down_sync(0xffffffffu, s, 1, 4);
            q += __shfl_down_sync(0xffffffffu, q, 2, 4);
            q += __shfl_down_sync(0xffffffffu, q, 1, 4);
            if (tg == 0) {
                red_s[w][mf*16 + hi*8 + g] = s;
                red_q[w][mf*16 + hi*8 + g] = q;
            }
        }
    __syncthreads();
    if (tid < 64) {
        int co = tid;
        int mw2 = co >> 5; int rem = co & 31;
        int mf = rem >> 4; int g8 = rem & 15;
        int hi = g8 >> 3;  int g2 = g8 & 7;
        int idx = mf*16 + hi*8 + g2;
        float s = 0.f, q = 0.f;
        #pragma unroll
        for (int nw2 = 0; nw2 < 7; ++nw2) {
            s += red_s[nw2*2 + mw2][idx];
            q += red_q[nw2*2 + mw2][idx];
        }
        g_bnsum2[co*NBLK + bl*TILES + tile] = s;
        g_bnsq2 [co*NBLK + bl*TILES + tile] = q;
    }
}

// ============================================================================
// K4b: final BN statistics. (unchanged)
// ============================================================================
__global__ __launch_bounds__(256) void k4b_stats() {
    int co  = blockIdx.x;
    int tid = threadIdx.x;
    float s = 0.f, q = 0.f;
    for (int i = tid; i < NBLK; i += 256) {
        s += g_bnsum2[co*NBLK + i];
        q += g_bnsq2 [co*NBLK + i];
    }
    #pragma unroll
    for (int off = 16; off > 0; off >>= 1) {
        s += __shfl_down_sync(0xffffffffu, s, off);
        q += __shfl_down_sync(0xffffffffu, q, off);
    }
    __shared__ float ws2[8], wq2[8];
    int wid = tid >> 5, lane = tid & 31;
    if (lane == 0) { ws2[wid] = s; wq2[wid] = q; }
    __syncthreads();
    if (tid == 0) {
        float S = 0.f, Q = 0.f;
        #pragma unroll
        for (int i = 0; i < 8; ++i) { S += ws2[i]; Q += wq2[i]; }
        const float invN = 1.0f / (float)(BLn * HWn);
        float mean = S * invN;
        float var  = Q * invN - mean*mean;
        g_mean[co]   = mean;
        g_invstd[co] = rsqrtf(var + 1e-5f);
    }
}

// ============================================================================
// K5: BN normalize + affine + SiLU -> d_out; reads fp16 y. (unchanged)
// ============================================================================
__global__ __launch_bounds__(256) void k5_bnsilu(const float* __restrict__ gamma,
                                                 const float* __restrict__ beta,
                                                 float* __restrict__ out) {
    int i4 = blockIdx.x * 256 + threadIdx.x;
    int c = ((i4 * 4) / HWn) & 63;
    uint2 yv = ((const uint2*)g_yh)[i4];
    __half2 h01 = *(__half2*)&yv.x;
    __half2 h23 = *(__half2*)&yv.y;
    float2 f01 = __half22float2(h01);
    float2 f23 = __half22float2(h23);
    float m = g_mean[c], is = g_invstd[c] * gamma[c], bt = beta[c];
    float4 o;
    o.x = (f01.x - m) * is + bt;
    o.y = (f01.y - m) * is + bt;
    o.z = (f23.x - m) * is + bt;
    o.w = (f23.y - m) * is + bt;
    o.x = o.x / (1.0f + __expf(-o.x));
    o.y = o.y / (1.0f + __expf(-o.y));
    o.z = o.z / (1.0f + __expf(-o.z));
    o.w = o.w / (1.0f + __expf(-o.w));
    ((float4*)out)[i4] = o;
}

// ============================================================================
extern "C" void kernel_launch(void* const* d_in, const int* in_sizes, int n_in,
                              void* d_out, int out_size) {
    const float* x          = (const float*)d_in[0];
    const float* temporal_w = (const float*)d_in[1];
    const float* temporal_b = (const float*)d_in[2];
    const float* fc_w       = (const float*)d_in[3];
    const float* fc_b       = (const float*)d_in[4];
    const float* conv_w     = (const float*)d_in[5];
    const float* conv_b     = (const float*)d_in[6];
    const float* bn_gamma   = (const float*)d_in[7];
    const float* bn_beta    = (const float*)d_in[8];
    float* out = (float*)d_out;

    static int configured = 0;
    if (!configured) {
        cudaFuncSetAttribute(k1t_dft,  cudaFuncAttributeMaxDynamicSharedMemorySize, K1T_SMEM);
        cudaFuncSetAttribute(k4t_conv, cudaFuncAttributeMaxDynamicSharedMemorySize, K4T_SMEM);
        configured = 1;
    }

    k0_prep<<<53, 512>>>(conv_w);                // Ah + WBh + WCh
    k1t_dft<<<BCn*Ln, 256, K1T_SMEM>>>(x);       // 4096 blocks, fp16 tensor DFT
    k2_ldft<<<BCn*4, 448>>>(x);
    k3_calib<<<BLn, 64>>>(temporal_w, temporal_b, fc_w, fc_b, conv_b);
    k4t_conv<<<dim3(TILES, BLn), 448, K4T_SMEM>>>(x, conv_w);
    k4b_stats<<<Cn, 256>>>();
    k5_bnsilu<<<NTOT/1024, 256>>>(bn_gamma, bn_beta, out);
}